// round 1
// baseline (speedup 1.0000x reference)
#include <cuda_runtime.h>
#include <math.h>

// Problem constants
#define kN  32
#define kC  512
#define kT  1024
#define kNT (kN * kT)   // 32768 tokens
#define kNB 2048        // codebook size

static __device__ __forceinline__ float mu_f()  { return 0.99f; }
static __device__ __forceinline__ float omm_f() { return (float)(1.0 - 0.99); } // matches JAX f32(1-MU)

// Output layout (tuple concatenated, float32):
// x_d_out (N,C,T) | commit | perplexity | new_codebook (NB,C) | code_sum_ema (NB,C) | code_count_ema (NB)
#define O_XD     0LL
#define O_COMMIT ((long long)kN * kC * kT)          // 16777216
#define O_PERP   (O_COMMIT + 1)
#define O_CB     (O_PERP + 1)
#define O_SUM    (O_CB + (long long)kNB * kC)
#define O_CNT    (O_SUM + (long long)kNB * kC)

// ---------------- scratch (device globals; no dynamic allocation) ----------------
__device__ float  g_xT[(long long)kNT * kC];  // x transposed to (NT, C) row-major, 64MB
__device__ float  g_cnorm[kNB];
__device__ int    g_idx[kNT];
__device__ int    g_count[kNB];
__device__ int    g_off[kNB + 1];
__device__ int    g_pos[kNB];
__device__ int    g_tok[kNT];
__device__ double g_commit;

// ---------------- kernels ----------------

__global__ void k_zero() {
    int i = blockIdx.x * blockDim.x + threadIdx.x;
    if (i < kNB) g_count[i] = 0;
    if (i == 0) g_commit = 0.0;
}

// x (N,C,T) -> g_xT (N*T, C)
__global__ void k_transpose(const float* __restrict__ x) {
    __shared__ float tile[32][33];
    int n  = blockIdx.z;
    int t0 = blockIdx.x * 32;
    int c0 = blockIdx.y * 32;
    int tx = threadIdx.x;
    for (int cy = threadIdx.y; cy < 32; cy += 8)
        tile[cy][tx] = x[((long long)n * kC + (c0 + cy)) * kT + (t0 + tx)];
    __syncthreads();
    for (int ty = threadIdx.y; ty < 32; ty += 8)
        g_xT[((long long)n * kT + (t0 + ty)) * kC + (c0 + tx)] = tile[tx][ty];
}

// cnorm[j] = sum_c codebook[j][c]^2  (one warp per code)
__global__ void k_cnorm(const float* __restrict__ cb) {
    int j = blockIdx.x * blockDim.y + threadIdx.y;
    if (j >= kNB) return;
    float s = 0.f;
    for (int c = threadIdx.x; c < kC; c += 32) {
        float v = cb[(long long)j * kC + c];
        s += v * v;
    }
    #pragma unroll
    for (int o = 16; o; o >>= 1) s += __shfl_xor_sync(0xffffffffu, s, o);
    if (threadIdx.x == 0) g_cnorm[j] = s;
}

// Fused GEMM + argmin: score[i][j] = cnorm[j] - 2 * <x_i, c_j>  (|x|^2 is row-constant)
// BM=128 tokens/block, loops all 2048 codes in BN=128 tiles, BK=16, 8x8 frags, 256 thr.
__global__ __launch_bounds__(256, 2) void k_argmin(const float* __restrict__ cb) {
    const int BM = 128, BN = 128, BK = 16, TM = 8, TN = 8;
    __shared__ float As[BK][BM + 4];
    __shared__ float Bs[BK][BN + 4];
    __shared__ float s_cn[BN];
    __shared__ float s_bv[BM];
    __shared__ int   s_bi[BM];
    __shared__ float s_rv[BM][17];
    __shared__ int   s_ri[BM][17];

    int tid = threadIdx.x;
    long long m0 = (long long)blockIdx.x * BM;
    int tm = (tid >> 4) * TM;
    int tn = (tid & 15) * TN;

    if (tid < BM) { s_bv[tid] = 3.4e38f; s_bi[tid] = 0; }
    __syncthreads();

    for (int n0 = 0; n0 < kNB; n0 += BN) {
        if (tid < BN) s_cn[tid] = g_cnorm[n0 + tid];
        float acc[TM][TN];
        #pragma unroll
        for (int i = 0; i < TM; i++)
            #pragma unroll
            for (int j = 0; j < TN; j++) acc[i][j] = 0.f;

        for (int k0 = 0; k0 < kC; k0 += BK) {
            // cooperative loads: 128 rows x 16 cols for A (tokens) and B (codes)
            #pragma unroll
            for (int l = 0; l < 2; l++) {
                int f   = tid + l * 256;        // 0..511
                int row = f >> 2;
                int k4  = (f & 3) * 4;
                float4 va = *(const float4*)&g_xT[(m0 + row) * kC + k0 + k4];
                As[k4 + 0][row] = va.x; As[k4 + 1][row] = va.y;
                As[k4 + 2][row] = va.z; As[k4 + 3][row] = va.w;
                float4 vb = *(const float4*)&cb[((long long)(n0 + row)) * kC + k0 + k4];
                Bs[k4 + 0][row] = vb.x; Bs[k4 + 1][row] = vb.y;
                Bs[k4 + 2][row] = vb.z; Bs[k4 + 3][row] = vb.w;
            }
            __syncthreads();
            #pragma unroll
            for (int k = 0; k < BK; k++) {
                float ra[TM], rb[TN];
                #pragma unroll
                for (int i = 0; i < TM; i++) ra[i] = As[k][tm + i];
                #pragma unroll
                for (int j = 0; j < TN; j++) rb[j] = Bs[k][tn + j];
                #pragma unroll
                for (int i = 0; i < TM; i++)
                    #pragma unroll
                    for (int j = 0; j < TN; j++) acc[i][j] += ra[i] * rb[j];
            }
            __syncthreads();
        }

        // per-thread argmin over its 8 columns (ascending j => first-min tie-break)
        #pragma unroll
        for (int i = 0; i < TM; i++) {
            float bv = 3.4e38f; int bi = 0;
            #pragma unroll
            for (int j = 0; j < TN; j++) {
                float sc = s_cn[tn + j] - 2.0f * acc[i][j];
                if (sc < bv) { bv = sc; bi = n0 + tn + j; }
            }
            s_rv[tm + i][tid & 15] = bv;
            s_ri[tm + i][tid & 15] = bi;
        }
        __syncthreads();
        if (tid < BM) {
            float bv = s_bv[tid]; int bi = s_bi[tid];
            #pragma unroll
            for (int g = 0; g < 16; g++) {       // ascending column groups
                float v = s_rv[tid][g];
                if (v < bv) { bv = v; bi = s_ri[tid][g]; }
            }
            s_bv[tid] = bv; s_bi[tid] = bi;
        }
        __syncthreads();
    }
    if (tid < BM) g_idx[m0 + tid] = s_bi[tid];
}

__global__ void k_count() {
    int i = blockIdx.x * blockDim.x + threadIdx.x;
    if (i < kNT) atomicAdd(&g_count[g_idx[i]], 1);
}

// exclusive scan of 2048 counts (single block, 1024 threads, pair-per-thread)
__global__ void k_scan() {
    __shared__ int p[1024];
    int tid = threadIdx.x;
    int a = g_count[2 * tid], b = g_count[2 * tid + 1];
    p[tid] = a + b;
    __syncthreads();
    for (int off = 1; off < 1024; off <<= 1) {
        int v = (tid >= off) ? p[tid - off] : 0;
        __syncthreads();
        p[tid] += v;
        __syncthreads();
    }
    int base = p[tid] - a - b;
    g_off[2 * tid] = base;       g_off[2 * tid + 1] = base + a;
    g_pos[2 * tid] = base;       g_pos[2 * tid + 1] = base + a;
    if (tid == 1023) g_off[kNB] = p[tid];
}

__global__ void k_scatter() {
    int i = blockIdx.x * blockDim.x + threadIdx.x;
    if (i < kNT) {
        int j = g_idx[i];
        int pos = atomicAdd(&g_pos[j], 1);
        g_tok[pos] = i;
    }
}

// per-code: sorted deterministic segment sum + EMA + codebook update + EMA outputs
__global__ void k_update(const float* __restrict__ code_sum,
                         const float* __restrict__ code_count,
                         float* __restrict__ out) {
    __shared__ int toks[512];
    int j = blockIdx.x, tid = threadIdx.x;
    int beg = g_off[j], end = g_off[j + 1];
    int cnt = end - beg;
    int m = cnt < 512 ? cnt : 512;
    for (int i = tid; i < m; i += 128) toks[i] = g_tok[beg + i];
    __syncthreads();
    if (tid == 0 && m > 1) {  // small insertion sort for deterministic order
        for (int a2 = 1; a2 < m; a2++) {
            int key = toks[a2]; int b2 = a2 - 1;
            while (b2 >= 0 && toks[b2] > key) { toks[b2 + 1] = toks[b2]; b2--; }
            toks[b2 + 1] = key;
        }
    }
    __syncthreads();

    int c = tid * 4;
    float4 acc = make_float4(0.f, 0.f, 0.f, 0.f);
    for (int i = 0; i < m; i++) {
        float4 v = *(const float4*)&g_xT[(long long)toks[i] * kC + c];
        acc.x += v.x; acc.y += v.y; acc.z += v.z; acc.w += v.w;
    }
    for (int i = m; i < cnt; i++) {  // overflow path (unreachable for this distribution)
        float4 v = *(const float4*)&g_xT[(long long)g_tok[beg + i] * kC + c];
        acc.x += v.x; acc.y += v.y; acc.z += v.z; acc.w += v.w;
    }

    float MU = mu_f(), OMM = omm_f();
    float cema = MU * code_count[j] + OMM * (float)cnt;
    float4 os = *(const float4*)&code_sum[(long long)j * kC + c];
    float4 sema;
    sema.x = MU * os.x + OMM * acc.x;
    sema.y = MU * os.y + OMM * acc.y;
    sema.z = MU * os.z + OMM * acc.z;
    sema.w = MU * os.w + OMM * acc.w;
    float denom = fmaxf(cema, 1e-10f);
    bool usage = (cema >= 1.0f);
    float4 nb;
    if (usage) {
        nb.x = sema.x / denom; nb.y = sema.y / denom;
        nb.z = sema.z / denom; nb.w = sema.w / denom;
    } else {
        nb = *(const float4*)&g_xT[(long long)j * kC + c];  // x_flat[:nb_code] row j
    }
    long long o1 = O_CB + (long long)j * kC + c;
    out[o1 + 0] = nb.x; out[o1 + 1] = nb.y; out[o1 + 2] = nb.z; out[o1 + 3] = nb.w;
    long long o2 = O_SUM + (long long)j * kC + c;
    out[o2 + 0] = sema.x; out[o2 + 1] = sema.y; out[o2 + 2] = sema.z; out[o2 + 3] = sema.w;
    if (tid == 0) out[O_CNT + j] = cema;
}

// x_d_out (N,C,T) = x + (cb[idx] - x), plus commit-loss partial sums
__global__ void k_output(const float* __restrict__ x,
                         const float* __restrict__ cb,
                         float* __restrict__ out) {
    __shared__ float cbs[16 * 517];   // 16 codebook rows, padded stride (conflict-free)
    __shared__ float wsum[8];
    int b = blockIdx.x, tid = threadIdx.x;
    int i0 = b * 16;
    int n  = i0 / kT;
    int t0 = i0 % kT;
    {
        int r = tid >> 4, lane = tid & 15;
        int code = g_idx[i0 + r];
        const float* src = cb + (long long)code * kC;
        float* dst = cbs + r * 517;
        for (int q = lane * 4; q < kC; q += 64) {
            float4 v = *(const float4*)(src + q);
            dst[q] = v.x; dst[q + 1] = v.y; dst[q + 2] = v.z; dst[q + 3] = v.w;
        }
    }
    __syncthreads();

    int tl = tid & 15, grp = tid >> 4;
    int t  = t0 + tl;
    const float* xn = x + ((long long)n * kC) * kT + t;
    float* on = out + O_XD + ((long long)n * kC) * kT + t;
    const float* crow = cbs + tl * 517;
    float part = 0.f;
    for (int c = grp; c < kC; c += 16) {
        float xv = xn[(long long)c * kT];
        float cv = crow[c];
        float d = cv - xv;
        on[(long long)c * kT] = xv + d;   // x + (x_d - x), matches reference elementwise
        part += d * d;
    }
    #pragma unroll
    for (int o = 16; o; o >>= 1) part += __shfl_xor_sync(0xffffffffu, part, o);
    if ((tid & 31) == 0) wsum[tid >> 5] = part;
    __syncthreads();
    if (tid == 0) {
        float s = 0.f;
        for (int w = 0; w < 8; w++) s += wsum[w];
        atomicAdd(&g_commit, (double)s);
    }
}

// perplexity + commit loss scalars
__global__ void k_scalars(float* __restrict__ out) {
    __shared__ float wsum[8];
    int tid = threadIdx.x;
    float total = (float)kNT + 1e-10f;   // sum(new_code_count) is exactly 32768
    float s = 0.f;
    for (int j = tid; j < kNB; j += 256) {
        float p = (float)g_count[j] / total;
        s += p * logf(p + 1e-7f);        // p==0 -> 0 * log(1e-7) == 0
    }
    #pragma unroll
    for (int o = 16; o; o >>= 1) s += __shfl_xor_sync(0xffffffffu, s, o);
    if ((tid & 31) == 0) wsum[tid >> 5] = s;
    __syncthreads();
    if (tid == 0) {
        float S = 0.f;
        for (int w = 0; w < 8; w++) S += wsum[w];
        out[O_PERP]   = expf(-S);
        out[O_COMMIT] = (float)(g_commit / ((double)kNT * (double)kC));
    }
}

// ---------------- launch ----------------
extern "C" void kernel_launch(void* const* d_in, const int* in_sizes, int n_in,
                              void* d_out, int out_size) {
    const float* x          = (const float*)d_in[0];
    const float* cb         = (const float*)d_in[1];
    const float* code_sum   = (const float*)d_in[2];
    const float* code_count = (const float*)d_in[3];
    float* out = (float*)d_out;

    k_zero<<<8, 256>>>();
    k_transpose<<<dim3(kT / 32, kC / 32, kN), dim3(32, 8)>>>(x);
    k_cnorm<<<kNB / 4, dim3(32, 4)>>>(cb);
    k_argmin<<<kNT / 128, 256>>>(cb);
    k_count<<<kNT / 256, 256>>>();
    k_scan<<<1, 1024>>>();
    k_scatter<<<kNT / 256, 256>>>();
    k_update<<<kNB, 128>>>(code_sum, code_count, out);
    k_output<<<kNT / 16, 256>>>(x, cb, out);
    k_scalars<<<1, 256>>>(out);
}

// round 3
// speedup vs baseline: 1.4396x; 1.4396x over previous
#include <cuda_runtime.h>
#include <cuda_bf16.h>
#include <math.h>
#include <stdint.h>

// Problem constants
#define kN  32
#define kC  512
#define kT  1024
#define kNT (kN * kT)   // 32768 tokens
#define kNB 2048        // codebook size
#define CAP 64          // max candidates per token
#define DELTA 3.0f      // coarse-score candidate margin

static __device__ __forceinline__ float mu_f()  { return 0.99f; }
static __device__ __forceinline__ float omm_f() { return (float)(1.0 - 0.99); }

// Output layout (tuple concatenated, float32):
// x_d_out (N,C,T) | commit | perplexity | new_codebook (NB,C) | code_sum_ema (NB,C) | code_count_ema (NB)
#define O_XD     0LL
#define O_COMMIT ((long long)kN * kC * kT)
#define O_PERP   (O_COMMIT + 1)
#define O_CB     (O_PERP + 1)
#define O_SUM    (O_CB + (long long)kNB * kC)
#define O_CNT    (O_SUM + (long long)kNB * kC)

// ---------------- scratch ----------------
__device__ float          g_xT[(long long)kNT * kC];   // fp32 x, (NT, C)
__device__ __nv_bfloat16  g_xbf[(long long)kNT * kC];  // bf16 x
__device__ __nv_bfloat16  g_cbbf[(long long)kNB * kC]; // bf16 codebook
__device__ float  g_cnorm[kNB];
__device__ int    g_cand[(long long)kNT * CAP];
__device__ int    g_ccnt[kNT];
__device__ int    g_idx[kNT];
__device__ int    g_count[kNB];
__device__ int    g_off[kNB + 1];
__device__ int    g_pos[kNB];
__device__ int    g_tok[kNT];
__device__ double g_commit;

// ---------------- helpers ----------------
static __device__ __forceinline__ uint32_t smem_u32(const void* p) {
    uint32_t a;
    asm("{ .reg .u64 t; cvta.to.shared.u64 t, %1; cvt.u32.u64 %0, t; }" : "=r"(a) : "l"(p));
    return a;
}

#define CP_ASYNC16(dst, src) \
    asm volatile("cp.async.cg.shared.global [%0], [%1], 16;" :: "r"(dst), "l"(src) : "memory")
#define CP_COMMIT() asm volatile("cp.async.commit_group;" ::: "memory")
#define CP_WAIT0()  asm volatile("cp.async.wait_group 0;" ::: "memory")
#define CP_WAIT1()  asm volatile("cp.async.wait_group 1;" ::: "memory")

static __device__ __forceinline__ void mma_bf16(float* d, const uint32_t* a, const uint32_t* b) {
    asm volatile("mma.sync.aligned.m16n8k16.row.col.f32.bf16.bf16.f32 "
        "{%0,%1,%2,%3}, {%4,%5,%6,%7}, {%8,%9}, {%0,%1,%2,%3};"
        : "+f"(d[0]), "+f"(d[1]), "+f"(d[2]), "+f"(d[3])
        : "r"(a[0]), "r"(a[1]), "r"(a[2]), "r"(a[3]), "r"(b[0]), "r"(b[1]));
}

// monotonic float <-> uint order encoding (for atomicMin on floats incl. negatives)
static __device__ __forceinline__ unsigned fenc(float f) {
    unsigned u = __float_as_uint(f);
    return u ^ ((unsigned)((int)u >> 31) | 0x80000000u);
}
static __device__ __forceinline__ float fdec(unsigned u) {
    unsigned v = (u & 0x80000000u) ? (u ^ 0x80000000u) : ~u;
    return __uint_as_float(v);
}

// ---------------- small kernels ----------------
__global__ void k_zero() {
    int i = blockIdx.x * blockDim.x + threadIdx.x;
    if (i < kNB) g_count[i] = 0;
    if (i == 0) g_commit = 0.0;
}

// x (N,C,T) -> g_xT (N*T, C) fp32 + g_xbf bf16
__global__ void k_transpose(const float* __restrict__ x) {
    __shared__ float tile[32][33];
    int n  = blockIdx.z;
    int t0 = blockIdx.x * 32;
    int c0 = blockIdx.y * 32;
    int tx = threadIdx.x;
    for (int cy = threadIdx.y; cy < 32; cy += 8)
        tile[cy][tx] = x[((long long)n * kC + (c0 + cy)) * kT + (t0 + tx)];
    __syncthreads();
    for (int ty = threadIdx.y; ty < 32; ty += 8) {
        float v = tile[tx][ty];
        long long o = ((long long)n * kT + (t0 + ty)) * kC + (c0 + tx);
        g_xT[o]  = v;
        g_xbf[o] = __float2bfloat16(v);
    }
}

// cnorm (fp32) + codebook bf16 convert
__global__ void k_cnorm(const float* __restrict__ cb) {
    int j = blockIdx.x * blockDim.y + threadIdx.y;
    if (j >= kNB) return;
    float s = 0.f;
    for (int c = threadIdx.x; c < kC; c += 32) {
        float v = cb[(long long)j * kC + c];
        g_cbbf[(long long)j * kC + c] = __float2bfloat16(v);
        s += v * v;
    }
    #pragma unroll
    for (int o = 16; o; o >>= 1) s += __shfl_xor_sync(0xffffffffu, s, o);
    if (threadIdx.x == 0) g_cnorm[j] = s;
}

// ---------------- Phase 1: bf16 HMMA coarse GEMM + candidate epilogue ----------------
// smem layout (bytes):
//   A:    128 x 520 bf16 (pad 8) = 133120
//   B:    2 buffers x 128 x 72 bf16 (pad 8) = 36864
//   s_cn: 128 f32, s_rmin: 128 u32, s_cnt: 128 i32
#define SMP_A    0
#define SMP_B    133120
#define SMP_CN   169984
#define SMP_RMIN 170496
#define SMP_CNT  171008
#define SMP_TOT  171520
#define ASTRIDE  520
#define BSTRIDE  72

__global__ __launch_bounds__(256, 1) void k_phase1() {
    extern __shared__ char smem[];
    __nv_bfloat16* smA = (__nv_bfloat16*)(smem + SMP_A);
    __nv_bfloat16* smB = (__nv_bfloat16*)(smem + SMP_B);
    float*    s_cn   = (float*)(smem + SMP_CN);
    unsigned* s_rmin = (unsigned*)(smem + SMP_RMIN);
    int*      s_cnt  = (int*)(smem + SMP_CNT);

    const int tid  = threadIdx.x;
    const int lane = tid & 31, wid = tid >> 5;
    const int wm = wid >> 2, wn = wid & 3;          // 2 (M) x 4 (N) warps
    const int g  = lane >> 2;                        // group row 0..7
    const int qp = (lane & 3) * 2;                   // col-pair base in k / n
    const long long m0 = (long long)blockIdx.x * 128;
    const uint32_t sbase = smem_u32(smem);

    if (tid < 128) { s_rmin[tid] = 0xFFFFFFFFu; s_cnt[tid] = 0; }

    // A tile: 128 rows x 512 bf16 (stride 520)
    #pragma unroll
    for (int it = 0; it < 32; ++it) {
        int idx = tid + (it << 8);
        int r = idx >> 6, i16 = idx & 63;
        CP_ASYNC16(sbase + SMP_A + r * (ASTRIDE * 2) + i16 * 16,
                   &g_xbf[(m0 + r) * kC + i16 * 8]);
    }
    // B chunk 0 (codes 0..127, k 0..63)
    #pragma unroll
    for (int it = 0; it < 4; ++it) {
        int idx = tid + (it << 8);
        int r = idx >> 3, i16 = idx & 7;
        CP_ASYNC16(sbase + SMP_B + r * (BSTRIDE * 2) + i16 * 16,
                   &g_cbbf[(long long)r * kC + i16 * 8]);
    }
    CP_COMMIT();

    float acc[4][4][4];
    #pragma unroll
    for (int mf = 0; mf < 4; ++mf)
        #pragma unroll
        for (int nf = 0; nf < 4; ++nf)
            #pragma unroll
            for (int e = 0; e < 4; ++e) acc[mf][nf][e] = 0.f;

    for (int gc = 0; gc < 128; ++gc) {
        int nt = gc >> 3, kc = gc & 7;
        __syncthreads();   // prev iter mma + epilogue done (WAR on B buf & s_cn)
        if (kc == 0 && tid < 128) s_cn[tid] = g_cnorm[(nt << 7) + tid];
        if (gc + 1 < 128) {
            int nt2 = (gc + 1) >> 3, kc2 = (gc + 1) & 7, buf2 = (gc + 1) & 1;
            #pragma unroll
            for (int it = 0; it < 4; ++it) {
                int idx = tid + (it << 8);
                int r = idx >> 3, i16 = idx & 7;
                CP_ASYNC16(sbase + SMP_B + buf2 * (128 * BSTRIDE * 2) + r * (BSTRIDE * 2) + i16 * 16,
                           &g_cbbf[(long long)((nt2 << 7) + r) * kC + (kc2 << 6) + i16 * 8]);
            }
            CP_COMMIT();
            CP_WAIT1();
        } else {
            CP_WAIT0();
        }
        __syncthreads();   // chunk gc ready everywhere; s_cn visible

        const __nv_bfloat16* Bbuf = smB + (size_t)(gc & 1) * (128 * BSTRIDE);
        #pragma unroll
        for (int ks = 0; ks < 4; ++ks) {
            int k0 = (kc << 6) + (ks << 4);
            int kb = (ks << 4);
            uint32_t a[4][4], b[4][2];
            #pragma unroll
            for (int mf = 0; mf < 4; ++mf) {
                int r0 = wm * 64 + mf * 16 + g;
                a[mf][0] = *(const uint32_t*)(smA + r0 * ASTRIDE + k0 + qp);
                a[mf][1] = *(const uint32_t*)(smA + (r0 + 8) * ASTRIDE + k0 + qp);
                a[mf][2] = *(const uint32_t*)(smA + r0 * ASTRIDE + k0 + 8 + qp);
                a[mf][3] = *(const uint32_t*)(smA + (r0 + 8) * ASTRIDE + k0 + 8 + qp);
            }
            #pragma unroll
            for (int nf = 0; nf < 4; ++nf) {
                int n0 = wn * 32 + nf * 8 + g;
                b[nf][0] = *(const uint32_t*)(Bbuf + n0 * BSTRIDE + kb + qp);
                b[nf][1] = *(const uint32_t*)(Bbuf + n0 * BSTRIDE + kb + 8 + qp);
            }
            #pragma unroll
            for (int mf = 0; mf < 4; ++mf)
                #pragma unroll
                for (int nf = 0; nf < 4; ++nf)
                    mma_bf16(acc[mf][nf], a[mf], b[nf]);
        }

        if (kc == 7) {
            // -------- epilogue for N-tile nt --------
            // (1) per-row local mins -> smem atomicMin (row min includes this tile)
            #pragma unroll
            for (int mf = 0; mf < 4; ++mf) {
                float m0v = 3.4e38f, m1v = 3.4e38f;
                #pragma unroll
                for (int nf = 0; nf < 4; ++nf) {
                    int colL = wn * 32 + nf * 8 + qp;
                    float s0 = s_cn[colL]     - 2.0f * acc[mf][nf][0];
                    float s1 = s_cn[colL + 1] - 2.0f * acc[mf][nf][1];
                    float s2 = s_cn[colL]     - 2.0f * acc[mf][nf][2];
                    float s3 = s_cn[colL + 1] - 2.0f * acc[mf][nf][3];
                    m0v = fminf(m0v, fminf(s0, s1));
                    m1v = fminf(m1v, fminf(s2, s3));
                }
                int rowL = wm * 64 + mf * 16 + g;
                atomicMin(&s_rmin[rowL],     fenc(m0v));
                atomicMin(&s_rmin[rowL + 8], fenc(m1v));
            }
            __syncthreads();
            // (2) append candidates within DELTA of running min
            #pragma unroll
            for (int mf = 0; mf < 4; ++mf) {
                int rowL0 = wm * 64 + mf * 16 + g;
                float thr0 = fdec(s_rmin[rowL0])     + DELTA;
                float thr1 = fdec(s_rmin[rowL0 + 8]) + DELTA;
                #pragma unroll
                for (int nf = 0; nf < 4; ++nf) {
                    int colL = wn * 32 + nf * 8 + qp;
                    #pragma unroll
                    for (int e = 0; e < 4; ++e) {
                        int cL = colL + (e & 1);
                        float sc = s_cn[cL] - 2.0f * acc[mf][nf][e];
                        float thr = (e < 2) ? thr0 : thr1;
                        if (sc < thr) {
                            int rowL = rowL0 + ((e >> 1) << 3);
                            int p = atomicAdd(&s_cnt[rowL], 1);
                            if (p < CAP)
                                g_cand[(m0 + rowL) * CAP + p] = (nt << 7) + cL;
                        }
                    }
                }
                // zero accums for next N-tile
                #pragma unroll
                for (int nf = 0; nf < 4; ++nf)
                    #pragma unroll
                    for (int e = 0; e < 4; ++e) acc[mf][nf][e] = 0.f;
            }
        }
    }
    __syncthreads();
    if (tid < 128) g_ccnt[m0 + tid] = s_cnt[tid];
}

// ---------------- Phase 2: exact fp32 rescore of candidates ----------------
__global__ void k_rescore(const float* __restrict__ cb) {
    int w = (blockIdx.x * blockDim.x + threadIdx.x) >> 5;
    int lane = threadIdx.x & 31;
    if (w >= kNT) return;
    float xr[16];
    #pragma unroll
    for (int i = 0; i < 16; i++) xr[i] = g_xT[(long long)w * kC + lane + 32 * i];
    int cnt = g_ccnt[w];
    float bd = 3.4e38f; int bj = 0;
    if (cnt <= CAP) {
        for (int ci = 0; ci < cnt; ci++) {
            int j = g_cand[(long long)w * CAP + ci];
            const float* cr = cb + (long long)j * kC;
            float s = 0.f;
            #pragma unroll
            for (int i = 0; i < 16; i++) s += xr[i] * cr[lane + 32 * i];
            #pragma unroll
            for (int o = 16; o; o >>= 1) s += __shfl_xor_sync(0xffffffffu, s, o);
            float d = g_cnorm[j] - 2.0f * s;
            if (d < bd || (d == bd && j < bj)) { bd = d; bj = j; }
        }
    } else {  // overflow fallback: deterministic full scan
        for (int j = 0; j < kNB; j++) {
            const float* cr = cb + (long long)j * kC;
            float s = 0.f;
            #pragma unroll
            for (int i = 0; i < 16; i++) s += xr[i] * cr[lane + 32 * i];
            #pragma unroll
            for (int o = 16; o; o >>= 1) s += __shfl_xor_sync(0xffffffffu, s, o);
            float d = g_cnorm[j] - 2.0f * s;
            if (d < bd || (d == bd && j < bj)) { bd = d; bj = j; }
        }
    }
    if (lane == 0) g_idx[w] = bj;
}

// ---------------- histogram / scan / scatter ----------------
__global__ void k_count() {
    int i = blockIdx.x * blockDim.x + threadIdx.x;
    if (i < kNT) atomicAdd(&g_count[g_idx[i]], 1);
}

__global__ void k_scan() {
    __shared__ int p[1024];
    int tid = threadIdx.x;
    int a = g_count[2 * tid], b = g_count[2 * tid + 1];
    p[tid] = a + b;
    __syncthreads();
    for (int off = 1; off < 1024; off <<= 1) {
        int v = (tid >= off) ? p[tid - off] : 0;
        __syncthreads();
        p[tid] += v;
        __syncthreads();
    }
    int base = p[tid] - a - b;
    g_off[2 * tid] = base;       g_off[2 * tid + 1] = base + a;
    g_pos[2 * tid] = base;       g_pos[2 * tid + 1] = base + a;
    if (tid == 1023) g_off[kNB] = p[tid];
}

__global__ void k_scatter() {
    int i = blockIdx.x * blockDim.x + threadIdx.x;
    if (i < kNT) {
        int j = g_idx[i];
        int pos = atomicAdd(&g_pos[j], 1);
        g_tok[pos] = i;
    }
}

// ---------------- EMA update ----------------
__global__ void k_update(const float* __restrict__ code_sum,
                         const float* __restrict__ code_count,
                         float* __restrict__ out) {
    __shared__ int toks[512];
    int j = blockIdx.x, tid = threadIdx.x;
    int beg = g_off[j], end = g_off[j + 1];
    int cnt = end - beg;
    int m = cnt < 512 ? cnt : 512;
    for (int i = tid; i < m; i += 128) toks[i] = g_tok[beg + i];
    __syncthreads();
    if (tid == 0 && m > 1) {
        for (int a2 = 1; a2 < m; a2++) {
            int key = toks[a2]; int b2 = a2 - 1;
            while (b2 >= 0 && toks[b2] > key) { toks[b2 + 1] = toks[b2]; b2--; }
            toks[b2 + 1] = key;
        }
    }
    __syncthreads();

    int c = tid * 4;
    float4 acc = make_float4(0.f, 0.f, 0.f, 0.f);
    for (int i = 0; i < m; i++) {
        float4 v = *(const float4*)&g_xT[(long long)toks[i] * kC + c];
        acc.x += v.x; acc.y += v.y; acc.z += v.z; acc.w += v.w;
    }
    for (int i = m; i < cnt; i++) {
        float4 v = *(const float4*)&g_xT[(long long)g_tok[beg + i] * kC + c];
        acc.x += v.x; acc.y += v.y; acc.z += v.z; acc.w += v.w;
    }

    float MU = mu_f(), OMM = omm_f();
    float cema = MU * code_count[j] + OMM * (float)cnt;
    float4 os = *(const float4*)&code_sum[(long long)j * kC + c];
    float4 sema;
    sema.x = MU * os.x + OMM * acc.x;
    sema.y = MU * os.y + OMM * acc.y;
    sema.z = MU * os.z + OMM * acc.z;
    sema.w = MU * os.w + OMM * acc.w;
    float denom = fmaxf(cema, 1e-10f);
    bool usage = (cema >= 1.0f);
    float4 nb;
    if (usage) {
        nb.x = sema.x / denom; nb.y = sema.y / denom;
        nb.z = sema.z / denom; nb.w = sema.w / denom;
    } else {
        nb = *(const float4*)&g_xT[(long long)j * kC + c];
    }
    long long o1 = O_CB + (long long)j * kC + c;
    out[o1 + 0] = nb.x; out[o1 + 1] = nb.y; out[o1 + 2] = nb.z; out[o1 + 3] = nb.w;
    long long o2 = O_SUM + (long long)j * kC + c;
    out[o2 + 0] = sema.x; out[o2 + 1] = sema.y; out[o2 + 2] = sema.z; out[o2 + 3] = sema.w;
    if (tid == 0) out[O_CNT + j] = cema;
}

// ---------------- x_d_out + commit loss ----------------
__global__ void k_output(const float* __restrict__ x,
                         const float* __restrict__ cb,
                         float* __restrict__ out) {
    __shared__ float cbs[16 * 517];
    __shared__ float wsum[8];
    int b = blockIdx.x, tid = threadIdx.x;
    int i0 = b * 16;
    int n  = i0 / kT;
    int t0 = i0 % kT;
    {
        int r = tid >> 4, lane = tid & 15;
        int code = g_idx[i0 + r];
        const float* src = cb + (long long)code * kC;
        float* dst = cbs + r * 517;
        for (int q = lane * 4; q < kC; q += 64) {
            float4 v = *(const float4*)(src + q);
            dst[q] = v.x; dst[q + 1] = v.y; dst[q + 2] = v.z; dst[q + 3] = v.w;
        }
    }
    __syncthreads();

    int tl = tid & 15, grp = tid >> 4;
    int t  = t0 + tl;
    const float* xn = x + ((long long)n * kC) * kT + t;
    float* on = out + O_XD + ((long long)n * kC) * kT + t;
    const float* crow = cbs + tl * 517;
    float part = 0.f;
    for (int c = grp; c < kC; c += 16) {
        float xv = xn[(long long)c * kT];
        float cv = crow[c];
        float d = cv - xv;
        on[(long long)c * kT] = xv + d;
        part += d * d;
    }
    #pragma unroll
    for (int o = 16; o; o >>= 1) part += __shfl_xor_sync(0xffffffffu, part, o);
    if ((tid & 31) == 0) wsum[tid >> 5] = part;
    __syncthreads();
    if (tid == 0) {
        float s = 0.f;
        for (int w = 0; w < 8; w++) s += wsum[w];
        atomicAdd(&g_commit, (double)s);
    }
}

__global__ void k_scalars(float* __restrict__ out) {
    __shared__ float wsum[8];
    int tid = threadIdx.x;
    float total = (float)kNT + 1e-10f;
    float s = 0.f;
    for (int j = tid; j < kNB; j += 256) {
        float p = (float)g_count[j] / total;
        s += p * logf(p + 1e-7f);
    }
    #pragma unroll
    for (int o = 16; o; o >>= 1) s += __shfl_xor_sync(0xffffffffu, s, o);
    if ((tid & 31) == 0) wsum[tid >> 5] = s;
    __syncthreads();
    if (tid == 0) {
        float S = 0.f;
        for (int w = 0; w < 8; w++) S += wsum[w];
        out[O_PERP]   = expf(-S);
        out[O_COMMIT] = (float)(g_commit / ((double)kNT * (double)kC));
    }
}

// ---------------- launch ----------------
extern "C" void kernel_launch(void* const* d_in, const int* in_sizes, int n_in,
                              void* d_out, int out_size) {
    const float* x          = (const float*)d_in[0];
    const float* cb         = (const float*)d_in[1];
    const float* code_sum   = (const float*)d_in[2];
    const float* code_count = (const float*)d_in[3];
    float* out = (float*)d_out;

    cudaFuncSetAttribute(k_phase1, cudaFuncAttributeMaxDynamicSharedMemorySize, SMP_TOT);

    k_zero<<<8, 256>>>();
    k_transpose<<<dim3(kT / 32, kC / 32, kN), dim3(32, 8)>>>(x);
    k_cnorm<<<kNB / 4, dim3(32, 4)>>>(cb);
    k_phase1<<<kNT / 128, 256, SMP_TOT>>>();
    k_rescore<<<kNT / 8, 256>>>(cb);
    k_count<<<kNT / 256, 256>>>();
    k_scan<<<1, 1024>>>();
    k_scatter<<<kNT / 256, 256>>>();
    k_update<<<kNB, 128>>>(code_sum, code_count, out);
    k_output<<<kNT / 16, 256>>>(x, cb, out);
    k_scalars<<<1, 256>>>(out);
}

// round 4
// speedup vs baseline: 5.9578x; 4.1384x over previous
#include <cuda_runtime.h>
#include <cuda_bf16.h>
#include <math.h>
#include <stdint.h>

// Problem constants
#define kN  32
#define kC  512
#define kT  1024
#define kNT (kN * kT)   // 32768 tokens
#define kNB 2048        // codebook size
#define CAP 64          // max candidates per token
#define DELTA 3.0f      // coarse-score candidate margin
#define TOKCAP 2048     // per-code token buffer for sorted segment sum

static __device__ __forceinline__ float mu_f()  { return 0.99f; }
static __device__ __forceinline__ float omm_f() { return (float)(1.0 - 0.99); }

// Output layout (tuple concatenated, float32):
// x_d_out (N,C,T) | commit | perplexity | new_codebook (NB,C) | code_sum_ema (NB,C) | code_count_ema (NB)
#define O_XD     0LL
#define O_COMMIT ((long long)kN * kC * kT)
#define O_PERP   (O_COMMIT + 1)
#define O_CB     (O_PERP + 1)
#define O_SUM    (O_CB + (long long)kNB * kC)
#define O_CNT    (O_SUM + (long long)kNB * kC)

// ---------------- scratch ----------------
__device__ float          g_xT[(long long)kNT * kC];   // fp32 x, (NT, C)
__device__ __nv_bfloat16  g_xbf[(long long)kNT * kC];  // bf16 x
__device__ __nv_bfloat16  g_cbbf[(long long)kNB * kC]; // bf16 codebook
__device__ float  g_cnorm[kNB];
__device__ int    g_cand[(long long)kNT * CAP];
__device__ int    g_ccnt[kNT];
__device__ int    g_idx[kNT];
__device__ int    g_count[kNB];
__device__ int    g_off[kNB + 1];
__device__ int    g_pos[kNB];
__device__ int    g_tok[kNT];
__device__ double g_commit;

// ---------------- helpers ----------------
static __device__ __forceinline__ uint32_t smem_u32(const void* p) {
    uint32_t a;
    asm("{ .reg .u64 t; cvta.to.shared.u64 t, %1; cvt.u32.u64 %0, t; }" : "=r"(a) : "l"(p));
    return a;
}

#define CP_ASYNC16(dst, src) \
    asm volatile("cp.async.cg.shared.global [%0], [%1], 16;" :: "r"(dst), "l"(src) : "memory")
#define CP_COMMIT() asm volatile("cp.async.commit_group;" ::: "memory")
#define CP_WAIT0()  asm volatile("cp.async.wait_group 0;" ::: "memory")
#define CP_WAIT1()  asm volatile("cp.async.wait_group 1;" ::: "memory")

static __device__ __forceinline__ void mma_bf16(float* d, const uint32_t* a, const uint32_t* b) {
    asm volatile("mma.sync.aligned.m16n8k16.row.col.f32.bf16.bf16.f32 "
        "{%0,%1,%2,%3}, {%4,%5,%6,%7}, {%8,%9}, {%0,%1,%2,%3};"
        : "+f"(d[0]), "+f"(d[1]), "+f"(d[2]), "+f"(d[3])
        : "r"(a[0]), "r"(a[1]), "r"(a[2]), "r"(a[3]), "r"(b[0]), "r"(b[1]));
}

// monotonic float <-> uint order encoding (for atomicMin on floats incl. negatives)
static __device__ __forceinline__ unsigned fenc(float f) {
    unsigned u = __float_as_uint(f);
    return u ^ ((unsigned)((int)u >> 31) | 0x80000000u);
}
static __device__ __forceinline__ float fdec(unsigned u) {
    unsigned v = (u & 0x80000000u) ? (u ^ 0x80000000u) : ~u;
    return __uint_as_float(v);
}

// ---------------- small kernels ----------------
__global__ void k_zero() {
    int i = blockIdx.x * blockDim.x + threadIdx.x;
    if (i < kNB) g_count[i] = 0;
    if (i == 0) g_commit = 0.0;
}

// x (N,C,T) -> g_xT (N*T, C) fp32 + g_xbf bf16
__global__ void k_transpose(const float* __restrict__ x) {
    __shared__ float tile[32][33];
    int n  = blockIdx.z;
    int t0 = blockIdx.x * 32;
    int c0 = blockIdx.y * 32;
    int tx = threadIdx.x;
    for (int cy = threadIdx.y; cy < 32; cy += 8)
        tile[cy][tx] = x[((long long)n * kC + (c0 + cy)) * kT + (t0 + tx)];
    __syncthreads();
    for (int ty = threadIdx.y; ty < 32; ty += 8) {
        float v = tile[tx][ty];
        long long o = ((long long)n * kT + (t0 + ty)) * kC + (c0 + tx);
        g_xT[o]  = v;
        g_xbf[o] = __float2bfloat16(v);
    }
}

// cnorm (fp32) + codebook bf16 convert
__global__ void k_cnorm(const float* __restrict__ cb) {
    int j = blockIdx.x * blockDim.y + threadIdx.y;
    if (j >= kNB) return;
    float s = 0.f;
    for (int c = threadIdx.x; c < kC; c += 32) {
        float v = cb[(long long)j * kC + c];
        g_cbbf[(long long)j * kC + c] = __float2bfloat16(v);
        s += v * v;
    }
    #pragma unroll
    for (int o = 16; o; o >>= 1) s += __shfl_xor_sync(0xffffffffu, s, o);
    if (threadIdx.x == 0) g_cnorm[j] = s;
}

// ---------------- Phase 1: bf16 HMMA coarse GEMM + candidate epilogue ----------------
#define SMP_A    0
#define SMP_B    133120
#define SMP_CN   169984
#define SMP_RMIN 170496
#define SMP_CNT  171008
#define SMP_TOT  171520
#define ASTRIDE  520
#define BSTRIDE  72

__global__ __launch_bounds__(256, 1) void k_phase1() {
    extern __shared__ char smem[];
    __nv_bfloat16* smA = (__nv_bfloat16*)(smem + SMP_A);
    __nv_bfloat16* smB = (__nv_bfloat16*)(smem + SMP_B);
    float*    s_cn   = (float*)(smem + SMP_CN);
    unsigned* s_rmin = (unsigned*)(smem + SMP_RMIN);
    int*      s_cnt  = (int*)(smem + SMP_CNT);

    const int tid  = threadIdx.x;
    const int lane = tid & 31, wid = tid >> 5;
    const int wm = wid >> 2, wn = wid & 3;          // 2 (M) x 4 (N) warps
    const int g  = lane >> 2;                        // group row 0..7
    const int qp = (lane & 3) * 2;                   // col-pair base in k / n
    const long long m0 = (long long)blockIdx.x * 128;
    const uint32_t sbase = smem_u32(smem);

    if (tid < 128) { s_rmin[tid] = 0xFFFFFFFFu; s_cnt[tid] = 0; }

    // A tile: 128 rows x 512 bf16 (stride 520)
    #pragma unroll
    for (int it = 0; it < 32; ++it) {
        int idx = tid + (it << 8);
        int r = idx >> 6, i16 = idx & 63;
        CP_ASYNC16(sbase + SMP_A + r * (ASTRIDE * 2) + i16 * 16,
                   &g_xbf[(m0 + r) * kC + i16 * 8]);
    }
    // B chunk 0 (codes 0..127, k 0..63)
    #pragma unroll
    for (int it = 0; it < 4; ++it) {
        int idx = tid + (it << 8);
        int r = idx >> 3, i16 = idx & 7;
        CP_ASYNC16(sbase + SMP_B + r * (BSTRIDE * 2) + i16 * 16,
                   &g_cbbf[(long long)r * kC + i16 * 8]);
    }
    CP_COMMIT();

    float acc[4][4][4];
    #pragma unroll
    for (int mf = 0; mf < 4; ++mf)
        #pragma unroll
        for (int nf = 0; nf < 4; ++nf)
            #pragma unroll
            for (int e = 0; e < 4; ++e) acc[mf][nf][e] = 0.f;

    for (int gc = 0; gc < 128; ++gc) {
        int nt = gc >> 3, kc = gc & 7;
        __syncthreads();   // prev iter mma + epilogue done (WAR on B buf & s_cn)
        if (kc == 0 && tid < 128) s_cn[tid] = g_cnorm[(nt << 7) + tid];
        if (gc + 1 < 128) {
            int nt2 = (gc + 1) >> 3, kc2 = (gc + 1) & 7, buf2 = (gc + 1) & 1;
            #pragma unroll
            for (int it = 0; it < 4; ++it) {
                int idx = tid + (it << 8);
                int r = idx >> 3, i16 = idx & 7;
                CP_ASYNC16(sbase + SMP_B + buf2 * (128 * BSTRIDE * 2) + r * (BSTRIDE * 2) + i16 * 16,
                           &g_cbbf[(long long)((nt2 << 7) + r) * kC + (kc2 << 6) + i16 * 8]);
            }
            CP_COMMIT();
            CP_WAIT1();
        } else {
            CP_WAIT0();
        }
        __syncthreads();   // chunk gc ready everywhere; s_cn visible

        const __nv_bfloat16* Bbuf = smB + (size_t)(gc & 1) * (128 * BSTRIDE);
        #pragma unroll
        for (int ks = 0; ks < 4; ++ks) {
            int k0 = (kc << 6) + (ks << 4);
            int kb = (ks << 4);
            uint32_t a[4][4], b[4][2];
            #pragma unroll
            for (int mf = 0; mf < 4; ++mf) {
                int r0 = wm * 64 + mf * 16 + g;
                a[mf][0] = *(const uint32_t*)(smA + r0 * ASTRIDE + k0 + qp);
                a[mf][1] = *(const uint32_t*)(smA + (r0 + 8) * ASTRIDE + k0 + qp);
                a[mf][2] = *(const uint32_t*)(smA + r0 * ASTRIDE + k0 + 8 + qp);
                a[mf][3] = *(const uint32_t*)(smA + (r0 + 8) * ASTRIDE + k0 + 8 + qp);
            }
            #pragma unroll
            for (int nf = 0; nf < 4; ++nf) {
                int n0 = wn * 32 + nf * 8 + g;
                b[nf][0] = *(const uint32_t*)(Bbuf + n0 * BSTRIDE + kb + qp);
                b[nf][1] = *(const uint32_t*)(Bbuf + n0 * BSTRIDE + kb + 8 + qp);
            }
            #pragma unroll
            for (int mf = 0; mf < 4; ++mf)
                #pragma unroll
                for (int nf = 0; nf < 4; ++nf)
                    mma_bf16(acc[mf][nf], a[mf], b[nf]);
        }

        if (kc == 7) {
            // -------- epilogue for N-tile nt --------
            #pragma unroll
            for (int mf = 0; mf < 4; ++mf) {
                float m0v = 3.4e38f, m1v = 3.4e38f;
                #pragma unroll
                for (int nf = 0; nf < 4; ++nf) {
                    int colL = wn * 32 + nf * 8 + qp;
                    float s0 = s_cn[colL]     - 2.0f * acc[mf][nf][0];
                    float s1 = s_cn[colL + 1] - 2.0f * acc[mf][nf][1];
                    float s2 = s_cn[colL]     - 2.0f * acc[mf][nf][2];
                    float s3 = s_cn[colL + 1] - 2.0f * acc[mf][nf][3];
                    m0v = fminf(m0v, fminf(s0, s1));
                    m1v = fminf(m1v, fminf(s2, s3));
                }
                int rowL = wm * 64 + mf * 16 + g;
                atomicMin(&s_rmin[rowL],     fenc(m0v));
                atomicMin(&s_rmin[rowL + 8], fenc(m1v));
            }
            __syncthreads();
            #pragma unroll
            for (int mf = 0; mf < 4; ++mf) {
                int rowL0 = wm * 64 + mf * 16 + g;
                float thr0 = fdec(s_rmin[rowL0])     + DELTA;
                float thr1 = fdec(s_rmin[rowL0 + 8]) + DELTA;
                #pragma unroll
                for (int nf = 0; nf < 4; ++nf) {
                    int colL = wn * 32 + nf * 8 + qp;
                    #pragma unroll
                    for (int e = 0; e < 4; ++e) {
                        int cL = colL + (e & 1);
                        float sc = s_cn[cL] - 2.0f * acc[mf][nf][e];
                        float thr = (e < 2) ? thr0 : thr1;
                        if (sc < thr) {
                            int rowL = rowL0 + ((e >> 1) << 3);
                            int p = atomicAdd(&s_cnt[rowL], 1);
                            if (p < CAP)
                                g_cand[(m0 + rowL) * CAP + p] = (nt << 7) + cL;
                        }
                    }
                }
                #pragma unroll
                for (int nf = 0; nf < 4; ++nf)
                    #pragma unroll
                    for (int e = 0; e < 4; ++e) acc[mf][nf][e] = 0.f;
            }
        }
    }
    __syncthreads();
    if (tid < 128) g_ccnt[m0 + tid] = s_cnt[tid];
}

// ---------------- Phase 2: exact fp32 rescore of candidates ----------------
__global__ void k_rescore(const float* __restrict__ cb) {
    int w = (blockIdx.x * blockDim.x + threadIdx.x) >> 5;
    int lane = threadIdx.x & 31;
    if (w >= kNT) return;
    float xr[16];
    #pragma unroll
    for (int i = 0; i < 16; i++) xr[i] = g_xT[(long long)w * kC + lane + 32 * i];
    int cnt = g_ccnt[w];
    float bd = 3.4e38f; int bj = 0;
    if (cnt <= CAP) {
        for (int ci = 0; ci < cnt; ci++) {
            int j = g_cand[(long long)w * CAP + ci];
            const float* cr = cb + (long long)j * kC;
            float s = 0.f;
            #pragma unroll
            for (int i = 0; i < 16; i++) s += xr[i] * cr[lane + 32 * i];
            #pragma unroll
            for (int o = 16; o; o >>= 1) s += __shfl_xor_sync(0xffffffffu, s, o);
            float d = g_cnorm[j] - 2.0f * s;
            if (d < bd || (d == bd && j < bj)) { bd = d; bj = j; }
        }
    } else {  // overflow fallback: deterministic full scan
        for (int j = 0; j < kNB; j++) {
            const float* cr = cb + (long long)j * kC;
            float s = 0.f;
            #pragma unroll
            for (int i = 0; i < 16; i++) s += xr[i] * cr[lane + 32 * i];
            #pragma unroll
            for (int o = 16; o; o >>= 1) s += __shfl_xor_sync(0xffffffffu, s, o);
            float d = g_cnorm[j] - 2.0f * s;
            if (d < bd || (d == bd && j < bj)) { bd = d; bj = j; }
        }
    }
    if (lane == 0) g_idx[w] = bj;
}

// ---------------- histogram / scan / scatter ----------------
__global__ void k_count() {
    int i = blockIdx.x * blockDim.x + threadIdx.x;
    if (i < kNT) atomicAdd(&g_count[g_idx[i]], 1);
}

__global__ void k_scan() {
    __shared__ int p[1024];
    int tid = threadIdx.x;
    int a = g_count[2 * tid], b = g_count[2 * tid + 1];
    p[tid] = a + b;
    __syncthreads();
    for (int off = 1; off < 1024; off <<= 1) {
        int v = (tid >= off) ? p[tid - off] : 0;
        __syncthreads();
        p[tid] += v;
        __syncthreads();
    }
    int base = p[tid] - a - b;
    g_off[2 * tid] = base;       g_off[2 * tid + 1] = base + a;
    g_pos[2 * tid] = base;       g_pos[2 * tid + 1] = base + a;
    if (tid == 1023) g_off[kNB] = p[tid];
}

__global__ void k_scatter() {
    int i = blockIdx.x * blockDim.x + threadIdx.x;
    if (i < kNT) {
        int j = g_idx[i];
        int pos = atomicAdd(&g_pos[j], 1);
        g_tok[pos] = i;
    }
}

// ---------------- EMA update (parallel odd-even sort, no serial insertion sort) ----------------
__global__ void k_update(const float* __restrict__ code_sum,
                         const float* __restrict__ code_count,
                         float* __restrict__ out) {
    __shared__ int toks[TOKCAP];
    int j = blockIdx.x, tid = threadIdx.x;
    int beg = g_off[j], end = g_off[j + 1];
    int cnt = end - beg;
    int m = cnt < TOKCAP ? cnt : TOKCAP;
    for (int i = tid; i < m; i += 128) toks[i] = g_tok[beg + i];
    __syncthreads();
    // parallel odd-even transposition sort: m phases, all threads participate
    for (int phase = 0; phase < m; ++phase) {
        int start = phase & 1;
        for (int k2 = 2 * tid + start; k2 + 1 < m; k2 += 256) {
            int a2 = toks[k2], b2 = toks[k2 + 1];
            if (a2 > b2) { toks[k2] = b2; toks[k2 + 1] = a2; }
        }
        __syncthreads();
    }

    int c = tid * 4;
    float4 acc = make_float4(0.f, 0.f, 0.f, 0.f);
    for (int i = 0; i < m; i++) {
        float4 v = *(const float4*)&g_xT[(long long)toks[i] * kC + c];
        acc.x += v.x; acc.y += v.y; acc.z += v.z; acc.w += v.w;
    }
    for (int i = m; i < cnt; i++) {  // overflow tail (effectively unreachable)
        float4 v = *(const float4*)&g_xT[(long long)g_tok[beg + i] * kC + c];
        acc.x += v.x; acc.y += v.y; acc.z += v.z; acc.w += v.w;
    }

    float MU = mu_f(), OMM = omm_f();
    float cema = MU * code_count[j] + OMM * (float)cnt;
    float4 os = *(const float4*)&code_sum[(long long)j * kC + c];
    float4 sema;
    sema.x = MU * os.x + OMM * acc.x;
    sema.y = MU * os.y + OMM * acc.y;
    sema.z = MU * os.z + OMM * acc.z;
    sema.w = MU * os.w + OMM * acc.w;
    float denom = fmaxf(cema, 1e-10f);
    bool usage = (cema >= 1.0f);
    float4 nb;
    if (usage) {
        nb.x = sema.x / denom; nb.y = sema.y / denom;
        nb.z = sema.z / denom; nb.w = sema.w / denom;
    } else {
        nb = *(const float4*)&g_xT[(long long)j * kC + c];
    }
    long long o1 = O_CB + (long long)j * kC + c;
    out[o1 + 0] = nb.x; out[o1 + 1] = nb.y; out[o1 + 2] = nb.z; out[o1 + 3] = nb.w;
    long long o2 = O_SUM + (long long)j * kC + c;
    out[o2 + 0] = sema.x; out[o2 + 1] = sema.y; out[o2 + 2] = sema.z; out[o2 + 3] = sema.w;
    if (tid == 0) out[O_CNT + j] = cema;
}

// ---------------- x_d_out + commit loss ----------------
__global__ void k_output(const float* __restrict__ x,
                         const float* __restrict__ cb,
                         float* __restrict__ out) {
    __shared__ float cbs[16 * 517];
    __shared__ float wsum[8];
    int b = blockIdx.x, tid = threadIdx.x;
    int i0 = b * 16;
    int n  = i0 / kT;
    int t0 = i0 % kT;
    {
        int r = tid >> 4, lane = tid & 15;
        int code = g_idx[i0 + r];
        const float* src = cb + (long long)code * kC;
        float* dst = cbs + r * 517;
        for (int q = lane * 4; q < kC; q += 64) {
            float4 v = *(const float4*)(src + q);
            dst[q] = v.x; dst[q + 1] = v.y; dst[q + 2] = v.z; dst[q + 3] = v.w;
        }
    }
    __syncthreads();

    int tl = tid & 15, grp = tid >> 4;
    int t  = t0 + tl;
    const float* xn = x + ((long long)n * kC) * kT + t;
    float* on = out + O_XD + ((long long)n * kC) * kT + t;
    const float* crow = cbs + tl * 517;
    float part = 0.f;
    for (int c = grp; c < kC; c += 16) {
        float xv = xn[(long long)c * kT];
        float cv = crow[c];
        float d = cv - xv;
        on[(long long)c * kT] = xv + d;
        part += d * d;
    }
    #pragma unroll
    for (int o = 16; o; o >>= 1) part += __shfl_xor_sync(0xffffffffu, part, o);
    if ((tid & 31) == 0) wsum[tid >> 5] = part;
    __syncthreads();
    if (tid == 0) {
        float s = 0.f;
        for (int w = 0; w < 8; w++) s += wsum[w];
        atomicAdd(&g_commit, (double)s);
    }
}

__global__ void k_scalars(float* __restrict__ out) {
    __shared__ float wsum[8];
    int tid = threadIdx.x;
    float total = (float)kNT + 1e-10f;
    float s = 0.f;
    for (int j = tid; j < kNB; j += 256) {
        float p = (float)g_count[j] / total;
        s += p * logf(p + 1e-7f);
    }
    #pragma unroll
    for (int o = 16; o; o >>= 1) s += __shfl_xor_sync(0xffffffffu, s, o);
    if ((tid & 31) == 0) wsum[tid >> 5] = s;
    __syncthreads();
    if (tid == 0) {
        float S = 0.f;
        for (int w = 0; w < 8; w++) S += wsum[w];
        out[O_PERP]   = expf(-S);
        out[O_COMMIT] = (float)(g_commit / ((double)kNT * (double)kC));
    }
}

// ---------------- launch ----------------
extern "C" void kernel_launch(void* const* d_in, const int* in_sizes, int n_in,
                              void* d_out, int out_size) {
    const float* x          = (const float*)d_in[0];
    const float* cb         = (const float*)d_in[1];
    const float* code_sum   = (const float*)d_in[2];
    const float* code_count = (const float*)d_in[3];
    float* out = (float*)d_out;

    cudaFuncSetAttribute(k_phase1, cudaFuncAttributeMaxDynamicSharedMemorySize, SMP_TOT);

    k_zero<<<8, 256>>>();
    k_transpose<<<dim3(kT / 32, kC / 32, kN), dim3(32, 8)>>>(x);
    k_cnorm<<<kNB / 4, dim3(32, 4)>>>(cb);
    k_phase1<<<kNT / 128, 256, SMP_TOT>>>();
    k_rescore<<<kNT / 8, 256>>>(cb);
    k_count<<<kNT / 256, 256>>>();
    k_scan<<<1, 1024>>>();
    k_scatter<<<kNT / 256, 256>>>();
    k_update<<<kNB, 128>>>(code_sum, code_count, out);
    k_output<<<kNT / 16, 256>>>(x, cb, out);
    k_scalars<<<1, 256>>>(out);
}

// round 5
// speedup vs baseline: 6.2698x; 1.0524x over previous
#include <cuda_runtime.h>
#include <cuda_bf16.h>
#include <math.h>
#include <stdint.h>

// Problem constants
#define kN  32
#define kC  512
#define kT  1024
#define kNT (kN * kT)   // 32768 tokens
#define kNB 2048        // codebook size
#define CAP 64          // max candidates per token
#define DELTA 3.0f      // coarse-score candidate margin
#define TOKCAP 2048     // per-code token buffer for sorted segment sum

static __device__ __forceinline__ float mu_f()  { return 0.99f; }
static __device__ __forceinline__ float omm_f() { return (float)(1.0 - 0.99); }

// Output layout (tuple concatenated, float32):
// x_d_out (N,C,T) | commit | perplexity | new_codebook (NB,C) | code_sum_ema (NB,C) | code_count_ema (NB)
#define O_XD     0LL
#define O_COMMIT ((long long)kN * kC * kT)
#define O_PERP   (O_COMMIT + 1)
#define O_CB     (O_PERP + 1)
#define O_SUM    (O_CB + (long long)kNB * kC)
#define O_CNT    (O_SUM + (long long)kNB * kC)

// ---------------- scratch ----------------
__device__ float          g_xT[(long long)kNT * kC];   // fp32 x, (NT, C)
__device__ __nv_bfloat16  g_xbf[(long long)kNT * kC];  // bf16 x
__device__ __nv_bfloat16  g_cbbf[(long long)kNB * kC]; // bf16 codebook
__device__ float  g_cnorm[kNB];
__device__ int    g_cand[(long long)kNT * CAP];
__device__ int    g_ccnt[kNT];
__device__ int    g_idx[kNT];
__device__ int    g_count[kNB];
__device__ int    g_off[kNB + 1];
__device__ int    g_pos[kNB];
__device__ int    g_tok[kNT];
__device__ double g_commit;

// ---------------- helpers ----------------
static __device__ __forceinline__ uint32_t smem_u32(const void* p) {
    uint32_t a;
    asm("{ .reg .u64 t; cvta.to.shared.u64 t, %1; cvt.u32.u64 %0, t; }" : "=r"(a) : "l"(p));
    return a;
}

#define CP_ASYNC16(dst, src) \
    asm volatile("cp.async.cg.shared.global [%0], [%1], 16;" :: "r"(dst), "l"(src) : "memory")
#define CP_COMMIT() asm volatile("cp.async.commit_group;" ::: "memory")
#define CP_WAIT0()  asm volatile("cp.async.wait_group 0;" ::: "memory")
#define CP_WAIT1()  asm volatile("cp.async.wait_group 1;" ::: "memory")

static __device__ __forceinline__ void mma_bf16(float* d, const uint32_t* a, const uint32_t* b) {
    asm volatile("mma.sync.aligned.m16n8k16.row.col.f32.bf16.bf16.f32 "
        "{%0,%1,%2,%3}, {%4,%5,%6,%7}, {%8,%9}, {%0,%1,%2,%3};"
        : "+f"(d[0]), "+f"(d[1]), "+f"(d[2]), "+f"(d[3])
        : "r"(a[0]), "r"(a[1]), "r"(a[2]), "r"(a[3]), "r"(b[0]), "r"(b[1]));
}

static __device__ __forceinline__ void ldm_x4(uint32_t* r, uint32_t addr) {
    asm volatile("ldmatrix.sync.aligned.m8n8.x4.shared.b16 {%0,%1,%2,%3}, [%4];"
        : "=r"(r[0]), "=r"(r[1]), "=r"(r[2]), "=r"(r[3]) : "r"(addr));
}

// monotonic float <-> uint order encoding (for atomicMin on floats incl. negatives)
static __device__ __forceinline__ unsigned fenc(float f) {
    unsigned u = __float_as_uint(f);
    return u ^ ((unsigned)((int)u >> 31) | 0x80000000u);
}
static __device__ __forceinline__ float fdec(unsigned u) {
    unsigned v = (u & 0x80000000u) ? (u ^ 0x80000000u) : ~u;
    return __uint_as_float(v);
}

// ---------------- small kernels ----------------
__global__ void k_zero() {
    int i = blockIdx.x * blockDim.x + threadIdx.x;
    if (i < kNB) g_count[i] = 0;
    if (i == 0) g_commit = 0.0;
}

// x (N,C,T) -> g_xT (N*T, C) fp32 + g_xbf bf16
__global__ void k_transpose(const float* __restrict__ x) {
    __shared__ float tile[32][33];
    int n  = blockIdx.z;
    int t0 = blockIdx.x * 32;
    int c0 = blockIdx.y * 32;
    int tx = threadIdx.x;
    for (int cy = threadIdx.y; cy < 32; cy += 8)
        tile[cy][tx] = x[((long long)n * kC + (c0 + cy)) * kT + (t0 + tx)];
    __syncthreads();
    for (int ty = threadIdx.y; ty < 32; ty += 8) {
        float v = tile[tx][ty];
        long long o = ((long long)n * kT + (t0 + ty)) * kC + (c0 + tx);
        g_xT[o]  = v;
        g_xbf[o] = __float2bfloat16(v);
    }
}

// cnorm (fp32) + codebook bf16 convert
__global__ void k_cnorm(const float* __restrict__ cb) {
    int j = blockIdx.x * blockDim.y + threadIdx.y;
    if (j >= kNB) return;
    float s = 0.f;
    for (int c = threadIdx.x; c < kC; c += 32) {
        float v = cb[(long long)j * kC + c];
        g_cbbf[(long long)j * kC + c] = __float2bfloat16(v);
        s += v * v;
    }
    #pragma unroll
    for (int o = 16; o; o >>= 1) s += __shfl_xor_sync(0xffffffffu, s, o);
    if (threadIdx.x == 0) g_cnorm[j] = s;
}

// ---------------- Phase 1: bf16 HMMA coarse GEMM + candidate epilogue ----------------
// M-tile 64 (2 CTAs/SM), N-tile 128, K-chunk 64, double-buffered B.
#define SMP_A    0                  // 64 x 520 bf16 = 66560 B
#define SMP_B    66560              // 2 x (128 x 72 bf16) = 36864 B
#define SMP_CN   103424             // 128 f32
#define SMP_RMIN 103936             // 64 u32
#define SMP_CNT  104192             // 64 i32
#define SMP_TOT  104448
#define ASTRIDE  520
#define BSTRIDE  72
#define BBUF_B   18432              // bytes per B buffer (128*72*2)

__global__ __launch_bounds__(256, 2) void k_phase1() {
    extern __shared__ char smem[];
    float*    s_cn   = (float*)(smem + SMP_CN);
    unsigned* s_rmin = (unsigned*)(smem + SMP_RMIN);
    int*      s_cnt  = (int*)(smem + SMP_CNT);

    const int tid  = threadIdx.x;
    const int lane = tid & 31, wid = tid >> 5;
    const int wm = wid >> 2, wn = wid & 3;          // 2 (M) x 4 (N) warps
    const int g  = lane >> 2;                        // group row 0..7
    const int qp = (lane & 3) * 2;                   // col-pair base
    const long long m0 = (long long)blockIdx.x * 64;
    const uint32_t sbase = smem_u32(smem);

    if (tid < 64) { s_rmin[tid] = 0xFFFFFFFFu; s_cnt[tid] = 0; }

    // A tile: 64 rows x 512 bf16 (stride 520)
    #pragma unroll
    for (int it = 0; it < 16; ++it) {
        int idx = tid + (it << 8);
        int r = idx >> 6, i16 = idx & 63;
        CP_ASYNC16(sbase + SMP_A + r * (ASTRIDE * 2) + i16 * 16,
                   &g_xbf[(m0 + r) * kC + i16 * 8]);
    }
    // B chunk 0 (codes 0..127, k 0..63)
    #pragma unroll
    for (int it = 0; it < 4; ++it) {
        int idx = tid + (it << 8);
        int r = idx >> 3, i16 = idx & 7;
        CP_ASYNC16(sbase + SMP_B + r * (BSTRIDE * 2) + i16 * 16,
                   &g_cbbf[(long long)r * kC + i16 * 8]);
    }
    CP_COMMIT();

    // ldmatrix lane addressing (constant parts)
    const uint32_t aAddrBase = sbase + SMP_A + (uint32_t)(wm * 32 + (lane & 15)) * (ASTRIDE * 2)
                             + ((lane >> 4) << 4);   // + mf*16*1040 + k0*2
    const int bRow = wn * 32 + ((lane >> 4) << 3) + (lane & 7);   // + p*16
    const uint32_t bKoff = ((lane >> 3) & 1) << 4;                 // +16B if k-hi half

    float acc[2][4][4];
    #pragma unroll
    for (int mf = 0; mf < 2; ++mf)
        #pragma unroll
        for (int nf = 0; nf < 4; ++nf)
            #pragma unroll
            for (int e = 0; e < 4; ++e) acc[mf][nf][e] = 0.f;

    for (int gc = 0; gc < 128; ++gc) {
        int nt = gc >> 3, kc = gc & 7;
        __syncthreads();   // prev iter mma + epilogue done (WAR on B buf & s_cn)
        if (kc == 0 && tid < 128) s_cn[tid] = g_cnorm[(nt << 7) + tid];
        if (gc + 1 < 128) {
            int nt2 = (gc + 1) >> 3, kc2 = (gc + 1) & 7, buf2 = (gc + 1) & 1;
            #pragma unroll
            for (int it = 0; it < 4; ++it) {
                int idx = tid + (it << 8);
                int r = idx >> 3, i16 = idx & 7;
                CP_ASYNC16(sbase + SMP_B + buf2 * BBUF_B + r * (BSTRIDE * 2) + i16 * 16,
                           &g_cbbf[(long long)((nt2 << 7) + r) * kC + (kc2 << 6) + i16 * 8]);
            }
            CP_COMMIT();
            CP_WAIT1();
        } else {
            CP_WAIT0();
        }
        __syncthreads();   // chunk gc ready everywhere; s_cn visible

        const uint32_t bBase = sbase + SMP_B + (gc & 1) * BBUF_B;
        #pragma unroll
        for (int ks = 0; ks < 4; ++ks) {
            int k0 = (kc << 6) + (ks << 4);
            int kb = (ks << 4);
            uint32_t a[2][4], b[4][2];
            #pragma unroll
            for (int mf = 0; mf < 2; ++mf)
                ldm_x4(a[mf], aAddrBase + (uint32_t)mf * (16 * ASTRIDE * 2) + (uint32_t)k0 * 2);
            #pragma unroll
            for (int p = 0; p < 2; ++p) {
                uint32_t t4[4];
                ldm_x4(t4, bBase + (uint32_t)(bRow + p * 16) * (BSTRIDE * 2) + (uint32_t)kb * 2 + bKoff);
                b[p * 2][0] = t4[0];  b[p * 2][1] = t4[1];
                b[p * 2 + 1][0] = t4[2];  b[p * 2 + 1][1] = t4[3];
            }
            #pragma unroll
            for (int mf = 0; mf < 2; ++mf)
                #pragma unroll
                for (int nf = 0; nf < 4; ++nf)
                    mma_bf16(acc[mf][nf], a[mf], b[nf]);
        }

        if (kc == 7) {
            // -------- epilogue for N-tile nt --------
            #pragma unroll
            for (int mf = 0; mf < 2; ++mf) {
                float m0v = 3.4e38f, m1v = 3.4e38f;
                #pragma unroll
                for (int nf = 0; nf < 4; ++nf) {
                    int colL = wn * 32 + nf * 8 + qp;
                    float s0 = s_cn[colL]     - 2.0f * acc[mf][nf][0];
                    float s1 = s_cn[colL + 1] - 2.0f * acc[mf][nf][1];
                    float s2 = s_cn[colL]     - 2.0f * acc[mf][nf][2];
                    float s3 = s_cn[colL + 1] - 2.0f * acc[mf][nf][3];
                    m0v = fminf(m0v, fminf(s0, s1));
                    m1v = fminf(m1v, fminf(s2, s3));
                }
                int rowL = wm * 32 + mf * 16 + g;
                atomicMin(&s_rmin[rowL],     fenc(m0v));
                atomicMin(&s_rmin[rowL + 8], fenc(m1v));
            }
            __syncthreads();
            #pragma unroll
            for (int mf = 0; mf < 2; ++mf) {
                int rowL0 = wm * 32 + mf * 16 + g;
                float thr0 = fdec(s_rmin[rowL0])     + DELTA;
                float thr1 = fdec(s_rmin[rowL0 + 8]) + DELTA;
                #pragma unroll
                for (int nf = 0; nf < 4; ++nf) {
                    int colL = wn * 32 + nf * 8 + qp;
                    #pragma unroll
                    for (int e = 0; e < 4; ++e) {
                        int cL = colL + (e & 1);
                        float sc = s_cn[cL] - 2.0f * acc[mf][nf][e];
                        float thr = (e < 2) ? thr0 : thr1;
                        if (sc < thr) {
                            int rowL = rowL0 + ((e >> 1) << 3);
                            int p = atomicAdd(&s_cnt[rowL], 1);
                            if (p < CAP)
                                g_cand[(m0 + rowL) * CAP + p] = (nt << 7) + cL;
                        }
                    }
                }
                #pragma unroll
                for (int nf = 0; nf < 4; ++nf)
                    #pragma unroll
                    for (int e = 0; e < 4; ++e) acc[mf][nf][e] = 0.f;
            }
        }
    }
    __syncthreads();
    if (tid < 64) g_ccnt[m0 + tid] = s_cnt[tid];
}

// ---------------- Phase 2: exact fp32 rescore of candidates (+ fused count) ----------------
__global__ void k_rescore(const float* __restrict__ cb) {
    int w = (blockIdx.x * blockDim.x + threadIdx.x) >> 5;
    int lane = threadIdx.x & 31;
    if (w >= kNT) return;
    float xr[16];
    #pragma unroll
    for (int i = 0; i < 16; i++) xr[i] = g_xT[(long long)w * kC + lane + 32 * i];
    int cnt = g_ccnt[w];
    float bd = 3.4e38f; int bj = 0;
    if (cnt <= CAP) {
        for (int ci = 0; ci < cnt; ci++) {
            int j = g_cand[(long long)w * CAP + ci];
            const float* cr = cb + (long long)j * kC;
            float s = 0.f;
            #pragma unroll
            for (int i = 0; i < 16; i++) s += xr[i] * cr[lane + 32 * i];
            #pragma unroll
            for (int o = 16; o; o >>= 1) s += __shfl_xor_sync(0xffffffffu, s, o);
            float d = g_cnorm[j] - 2.0f * s;
            if (d < bd || (d == bd && j < bj)) { bd = d; bj = j; }
        }
    } else {  // overflow fallback: deterministic full scan
        for (int j = 0; j < kNB; j++) {
            const float* cr = cb + (long long)j * kC;
            float s = 0.f;
            #pragma unroll
            for (int i = 0; i < 16; i++) s += xr[i] * cr[lane + 32 * i];
            #pragma unroll
            for (int o = 16; o; o >>= 1) s += __shfl_xor_sync(0xffffffffu, s, o);
            float d = g_cnorm[j] - 2.0f * s;
            if (d < bd || (d == bd && j < bj)) { bd = d; bj = j; }
        }
    }
    if (lane == 0) {
        g_idx[w] = bj;
        atomicAdd(&g_count[bj], 1);
    }
}

// ---------------- scan / scatter ----------------
__global__ void k_scan() {
    __shared__ int p[1024];
    int tid = threadIdx.x;
    int a = g_count[2 * tid], b = g_count[2 * tid + 1];
    p[tid] = a + b;
    __syncthreads();
    for (int off = 1; off < 1024; off <<= 1) {
        int v = (tid >= off) ? p[tid - off] : 0;
        __syncthreads();
        p[tid] += v;
        __syncthreads();
    }
    int base = p[tid] - a - b;
    g_off[2 * tid] = base;       g_off[2 * tid + 1] = base + a;
    g_pos[2 * tid] = base;       g_pos[2 * tid + 1] = base + a;
    if (tid == 1023) g_off[kNB] = p[tid];
}

__global__ void k_scatter() {
    int i = blockIdx.x * blockDim.x + threadIdx.x;
    if (i < kNT) {
        int j = g_idx[i];
        int pos = atomicAdd(&g_pos[j], 1);
        g_tok[pos] = i;
    }
}

// ---------------- EMA update (parallel odd-even sort) ----------------
__global__ void k_update(const float* __restrict__ code_sum,
                         const float* __restrict__ code_count,
                         float* __restrict__ out) {
    __shared__ int toks[TOKCAP];
    int j = blockIdx.x, tid = threadIdx.x;
    int beg = g_off[j], end = g_off[j + 1];
    int cnt = end - beg;
    int m = cnt < TOKCAP ? cnt : TOKCAP;
    for (int i = tid; i < m; i += 128) toks[i] = g_tok[beg + i];
    __syncthreads();
    for (int phase = 0; phase < m; ++phase) {
        int start = phase & 1;
        for (int k2 = 2 * tid + start; k2 + 1 < m; k2 += 256) {
            int a2 = toks[k2], b2 = toks[k2 + 1];
            if (a2 > b2) { toks[k2] = b2; toks[k2 + 1] = a2; }
        }
        __syncthreads();
    }

    int c = tid * 4;
    float4 acc = make_float4(0.f, 0.f, 0.f, 0.f);
    for (int i = 0; i < m; i++) {
        float4 v = *(const float4*)&g_xT[(long long)toks[i] * kC + c];
        acc.x += v.x; acc.y += v.y; acc.z += v.z; acc.w += v.w;
    }
    for (int i = m; i < cnt; i++) {
        float4 v = *(const float4*)&g_xT[(long long)g_tok[beg + i] * kC + c];
        acc.x += v.x; acc.y += v.y; acc.z += v.z; acc.w += v.w;
    }

    float MU = mu_f(), OMM = omm_f();
    float cema = MU * code_count[j] + OMM * (float)cnt;
    float4 os = *(const float4*)&code_sum[(long long)j * kC + c];
    float4 sema;
    sema.x = MU * os.x + OMM * acc.x;
    sema.y = MU * os.y + OMM * acc.y;
    sema.z = MU * os.z + OMM * acc.z;
    sema.w = MU * os.w + OMM * acc.w;
    float denom = fmaxf(cema, 1e-10f);
    bool usage = (cema >= 1.0f);
    float4 nb;
    if (usage) {
        nb.x = sema.x / denom; nb.y = sema.y / denom;
        nb.z = sema.z / denom; nb.w = sema.w / denom;
    } else {
        nb = *(const float4*)&g_xT[(long long)j * kC + c];
    }
    long long o1 = O_CB + (long long)j * kC + c;
    out[o1 + 0] = nb.x; out[o1 + 1] = nb.y; out[o1 + 2] = nb.z; out[o1 + 3] = nb.w;
    long long o2 = O_SUM + (long long)j * kC + c;
    out[o2 + 0] = sema.x; out[o2 + 1] = sema.y; out[o2 + 2] = sema.z; out[o2 + 3] = sema.w;
    if (tid == 0) out[O_CNT + j] = cema;
}

// ---------------- x_d_out + commit loss ----------------
__global__ void k_output(const float* __restrict__ x,
                         const float* __restrict__ cb,
                         float* __restrict__ out) {
    __shared__ float cbs[16 * 517];
    __shared__ float wsum[8];
    int b = blockIdx.x, tid = threadIdx.x;
    int i0 = b * 16;
    int n  = i0 / kT;
    int t0 = i0 % kT;
    {
        int r = tid >> 4, lane = tid & 15;
        int code = g_idx[i0 + r];
        const float* src = cb + (long long)code * kC;
        float* dst = cbs + r * 517;
        for (int q = lane * 4; q < kC; q += 64) {
            float4 v = *(const float4*)(src + q);
            dst[q] = v.x; dst[q + 1] = v.y; dst[q + 2] = v.z; dst[q + 3] = v.w;
        }
    }
    __syncthreads();

    int tl = tid & 15, grp = tid >> 4;
    int t  = t0 + tl;
    const float* xn = x + ((long long)n * kC) * kT + t;
    float* on = out + O_XD + ((long long)n * kC) * kT + t;
    const float* crow = cbs + tl * 517;
    float part = 0.f;
    for (int c = grp; c < kC; c += 16) {
        float xv = xn[(long long)c * kT];
        float cv = crow[c];
        float d = cv - xv;
        on[(long long)c * kT] = xv + d;
        part += d * d;
    }
    #pragma unroll
    for (int o = 16; o; o >>= 1) part += __shfl_xor_sync(0xffffffffu, part, o);
    if ((tid & 31) == 0) wsum[tid >> 5] = part;
    __syncthreads();
    if (tid == 0) {
        float s = 0.f;
        for (int w = 0; w < 8; w++) s += wsum[w];
        atomicAdd(&g_commit, (double)s);
    }
}

__global__ void k_scalars(float* __restrict__ out) {
    __shared__ float wsum[8];
    int tid = threadIdx.x;
    float total = (float)kNT + 1e-10f;
    float s = 0.f;
    for (int j = tid; j < kNB; j += 256) {
        float p = (float)g_count[j] / total;
        s += p * logf(p + 1e-7f);
    }
    #pragma unroll
    for (int o = 16; o; o >>= 1) s += __shfl_xor_sync(0xffffffffu, s, o);
    if ((tid & 31) == 0) wsum[tid >> 5] = s;
    __syncthreads();
    if (tid == 0) {
        float S = 0.f;
        for (int w = 0; w < 8; w++) S += wsum[w];
        out[O_PERP]   = expf(-S);
        out[O_COMMIT] = (float)(g_commit / ((double)kNT * (double)kC));
    }
}

// ---------------- launch ----------------
extern "C" void kernel_launch(void* const* d_in, const int* in_sizes, int n_in,
                              void* d_out, int out_size) {
    const float* x          = (const float*)d_in[0];
    const float* cb         = (const float*)d_in[1];
    const float* code_sum   = (const float*)d_in[2];
    const float* code_count = (const float*)d_in[3];
    float* out = (float*)d_out;

    cudaFuncSetAttribute(k_phase1, cudaFuncAttributeMaxDynamicSharedMemorySize, SMP_TOT);

    k_zero<<<8, 256>>>();
    k_transpose<<<dim3(kT / 32, kC / 32, kN), dim3(32, 8)>>>(x);
    k_cnorm<<<kNB / 4, dim3(32, 4)>>>(cb);
    k_phase1<<<kNT / 64, 256, SMP_TOT>>>();
    k_rescore<<<kNT / 8, 256>>>(cb);
    k_scan<<<1, 1024>>>();
    k_scatter<<<kNT / 256, 256>>>();
    k_update<<<kNB, 128>>>(code_sum, code_count, out);
    k_output<<<kNT / 16, 256>>>(x, cb, out);
    k_scalars<<<1, 256>>>(out);
}

// round 6
// speedup vs baseline: 6.4002x; 1.0208x over previous
#include <cuda_runtime.h>
#include <cuda_bf16.h>
#include <math.h>
#include <stdint.h>

// Problem constants
#define kN  32
#define kC  512
#define kT  1024
#define kNT (kN * kT)   // 32768 tokens
#define kNB 2048        // codebook size
#define CAP 64          // max candidates per token
#define DELTA 3.0f      // coarse-score candidate margin
#define TOKCAP 2048     // per-code token buffer for sorted segment sum

static __device__ __forceinline__ float mu_f()  { return 0.99f; }
static __device__ __forceinline__ float omm_f() { return (float)(1.0 - 0.99); }

// Output layout (tuple concatenated, float32):
// x_d_out (N,C,T) | commit | perplexity | new_codebook (NB,C) | code_sum_ema (NB,C) | code_count_ema (NB)
#define O_XD     0LL
#define O_COMMIT ((long long)kN * kC * kT)
#define O_PERP   (O_COMMIT + 1)
#define O_CB     (O_PERP + 1)
#define O_SUM    (O_CB + (long long)kNB * kC)
#define O_CNT    (O_SUM + (long long)kNB * kC)

// ---------------- scratch ----------------
__device__ float          g_xT[(long long)kNT * kC];   // fp32 x, (NT, C)
__device__ __nv_bfloat16  g_xbf[(long long)kNT * kC];  // bf16 x
__device__ __nv_bfloat16  g_cbbf[(long long)kNB * kC]; // bf16 codebook
__device__ float  g_cnorm[kNB];
__device__ int    g_cand[(long long)kNT * CAP];
__device__ int    g_ccnt[kNT];
__device__ int    g_idx[kNT];
__device__ int    g_count[kNB];
__device__ int    g_off[kNB + 1];
__device__ int    g_pos[kNB];
__device__ int    g_tok[kNT];
__device__ double g_commit;

// ---------------- helpers ----------------
static __device__ __forceinline__ uint32_t smem_u32(const void* p) {
    uint32_t a;
    asm("{ .reg .u64 t; cvta.to.shared.u64 t, %1; cvt.u32.u64 %0, t; }" : "=r"(a) : "l"(p));
    return a;
}

#define CP_ASYNC16(dst, src) \
    asm volatile("cp.async.cg.shared.global [%0], [%1], 16;" :: "r"(dst), "l"(src) : "memory")
#define CP_COMMIT() asm volatile("cp.async.commit_group;" ::: "memory")
#define CP_WAIT0()  asm volatile("cp.async.wait_group 0;" ::: "memory")
#define CP_WAIT2()  asm volatile("cp.async.wait_group 2;" ::: "memory")

static __device__ __forceinline__ void mma_bf16(float* d, const uint32_t* a, const uint32_t* b) {
    asm volatile("mma.sync.aligned.m16n8k16.row.col.f32.bf16.bf16.f32 "
        "{%0,%1,%2,%3}, {%4,%5,%6,%7}, {%8,%9}, {%0,%1,%2,%3};"
        : "+f"(d[0]), "+f"(d[1]), "+f"(d[2]), "+f"(d[3])
        : "r"(a[0]), "r"(a[1]), "r"(a[2]), "r"(a[3]), "r"(b[0]), "r"(b[1]));
}

static __device__ __forceinline__ void ldm_x4(uint32_t* r, uint32_t addr) {
    asm volatile("ldmatrix.sync.aligned.m8n8.x4.shared.b16 {%0,%1,%2,%3}, [%4];"
        : "=r"(r[0]), "=r"(r[1]), "=r"(r[2]), "=r"(r[3]) : "r"(addr));
}

// monotonic float <-> uint order encoding (for atomicMin on floats incl. negatives)
static __device__ __forceinline__ unsigned fenc(float f) {
    unsigned u = __float_as_uint(f);
    return u ^ ((unsigned)((int)u >> 31) | 0x80000000u);
}
static __device__ __forceinline__ float fdec(unsigned u) {
    unsigned v = (u & 0x80000000u) ? (u ^ 0x80000000u) : ~u;
    return __uint_as_float(v);
}

// ---------------- small kernels ----------------
__global__ void k_zero() {
    int i = blockIdx.x * blockDim.x + threadIdx.x;
    if (i < kNB) g_count[i] = 0;
    if (i == 0) g_commit = 0.0;
}

// x (N,C,T) -> g_xT (N*T, C) fp32 + g_xbf bf16
__global__ void k_transpose(const float* __restrict__ x) {
    __shared__ float tile[32][33];
    int n  = blockIdx.z;
    int t0 = blockIdx.x * 32;
    int c0 = blockIdx.y * 32;
    int tx = threadIdx.x;
    for (int cy = threadIdx.y; cy < 32; cy += 8)
        tile[cy][tx] = x[((long long)n * kC + (c0 + cy)) * kT + (t0 + tx)];
    __syncthreads();
    for (int ty = threadIdx.y; ty < 32; ty += 8) {
        float v = tile[tx][ty];
        long long o = ((long long)n * kT + (t0 + ty)) * kC + (c0 + tx);
        g_xT[o]  = v;
        g_xbf[o] = __float2bfloat16(v);
    }
}

// cnorm (fp32) + codebook bf16 convert
__global__ void k_cnorm(const float* __restrict__ cb) {
    int j = blockIdx.x * blockDim.y + threadIdx.y;
    if (j >= kNB) return;
    float s = 0.f;
    for (int c = threadIdx.x; c < kC; c += 32) {
        float v = cb[(long long)j * kC + c];
        g_cbbf[(long long)j * kC + c] = __float2bfloat16(v);
        s += v * v;
    }
    #pragma unroll
    for (int o = 16; o; o >>= 1) s += __shfl_xor_sync(0xffffffffu, s, o);
    if (threadIdx.x == 0) g_cnorm[j] = s;
}

// ---------------- Phase 1: bf16 HMMA coarse GEMM, 4-stage pipeline ----------------
// M-tile 64 (2 CTAs/SM), N-tile 128, K-chunk 32, 4 B-stage cp.async pipeline.
#define SMP_A    0                  // 64 x 520 bf16 = 66560 B
#define SMP_B    66560              // 4 x (128 x 40 bf16) = 40960 B
#define SMP_CN   107520             // 128 f32
#define SMP_RMIN 108032             // 64 u32
#define SMP_CNT  108288             // 64 i32
#define SMP_TOT  108544
#define ASTRIDE  520
#define BSTRIDE  40                 // 80 B rows: 20-bank shift/row -> ldmatrix conflict-free
#define BBUF_B   10240              // bytes per B stage (128*40*2)
#define NCHUNK   256                // (2048/128 N-tiles) * (512/32 k-chunks)

__global__ __launch_bounds__(256, 2) void k_phase1() {
    extern __shared__ char smem[];
    float*    s_cn   = (float*)(smem + SMP_CN);
    unsigned* s_rmin = (unsigned*)(smem + SMP_RMIN);
    int*      s_cnt  = (int*)(smem + SMP_CNT);

    const int tid  = threadIdx.x;
    const int lane = tid & 31, wid = tid >> 5;
    const int wm = wid >> 2, wn = wid & 3;          // 2 (M) x 4 (N) warps
    const int g  = lane >> 2;                        // group row 0..7
    const int qp = (lane & 3) * 2;                   // col-pair base
    const long long m0 = (long long)blockIdx.x * 64;
    const uint32_t sbase = smem_u32(smem);

    if (tid < 64) { s_rmin[tid] = 0xFFFFFFFFu; s_cnt[tid] = 0; }

    // prologue: A tile (64 x 512 bf16) + B chunk 0 in group 0; chunks 1,2 in groups 1,2
    #pragma unroll
    for (int it = 0; it < 16; ++it) {
        int idx = tid + (it << 8);
        int r = idx >> 6, i16 = idx & 63;
        CP_ASYNC16(sbase + SMP_A + r * (ASTRIDE * 2) + i16 * 16,
                   &g_xbf[(m0 + r) * kC + i16 * 8]);
    }
    #pragma unroll
    for (int pc = 0; pc < 3; ++pc) {      // chunks 0,1,2 (all nt=0, kc=pc)
        #pragma unroll
        for (int it = 0; it < 2; ++it) {
            int idx = tid + (it << 8);
            int r = idx >> 2, i16 = idx & 3;
            CP_ASYNC16(sbase + SMP_B + pc * BBUF_B + r * (BSTRIDE * 2) + i16 * 16,
                       &g_cbbf[(long long)r * kC + pc * 32 + i16 * 8]);
        }
        CP_COMMIT();
    }

    // ldmatrix lane addressing (constant parts)
    const uint32_t aAddrBase = sbase + SMP_A + (uint32_t)(wm * 32 + (lane & 15)) * (ASTRIDE * 2)
                             + ((lane >> 4) << 4);
    const int bRow = wn * 32 + ((lane >> 4) << 3) + (lane & 7);
    const uint32_t bKoff = ((lane >> 3) & 1) << 4;

    float acc[2][4][4];
    #pragma unroll
    for (int mf = 0; mf < 2; ++mf)
        #pragma unroll
        for (int nf = 0; nf < 4; ++nf)
            #pragma unroll
            for (int e = 0; e < 4; ++e) acc[mf][nf][e] = 0.f;

    for (int gc = 0; gc < NCHUNK; ++gc) {
        int nt = gc >> 4, kc = gc & 15;
        CP_WAIT2();        // own-thread: chunk gc landed (<=2 groups outstanding)
        __syncthreads();   // visibility of all threads' cp(gc); WAR fence for cp(gc+3)
        if (kc == 0 && tid < 128) s_cn[tid] = g_cnorm[(nt << 7) + tid];

        // -------- compute chunk gc (32 k-columns = 2 x k16) --------
        const uint32_t bBase = sbase + SMP_B + (gc & 3) * BBUF_B;
        #pragma unroll
        for (int ks = 0; ks < 2; ++ks) {
            int k0 = (kc << 5) + (ks << 4);
            uint32_t a[2][4], b[4][2];
            #pragma unroll
            for (int mf = 0; mf < 2; ++mf)
                ldm_x4(a[mf], aAddrBase + (uint32_t)mf * (16 * ASTRIDE * 2) + (uint32_t)k0 * 2);
            #pragma unroll
            for (int p = 0; p < 2; ++p) {
                uint32_t t4[4];
                ldm_x4(t4, bBase + (uint32_t)(bRow + p * 16) * (BSTRIDE * 2) + (uint32_t)(ks << 5) + bKoff);
                b[p * 2][0] = t4[0];      b[p * 2][1] = t4[1];
                b[p * 2 + 1][0] = t4[2];  b[p * 2 + 1][1] = t4[3];
            }
            #pragma unroll
            for (int mf = 0; mf < 2; ++mf)
                #pragma unroll
                for (int nf = 0; nf < 4; ++nf)
                    mma_bf16(acc[mf][nf], a[mf], b[nf]);
        }

        if (kc == 15) {
            // -------- epilogue for N-tile nt --------
            #pragma unroll
            for (int mf = 0; mf < 2; ++mf) {
                float m0v = 3.4e38f, m1v = 3.4e38f;
                #pragma unroll
                for (int nf = 0; nf < 4; ++nf) {
                    int colL = wn * 32 + nf * 8 + qp;
                    float s0 = s_cn[colL]     - 2.0f * acc[mf][nf][0];
                    float s1 = s_cn[colL + 1] - 2.0f * acc[mf][nf][1];
                    float s2 = s_cn[colL]     - 2.0f * acc[mf][nf][2];
                    float s3 = s_cn[colL + 1] - 2.0f * acc[mf][nf][3];
                    m0v = fminf(m0v, fminf(s0, s1));
                    m1v = fminf(m1v, fminf(s2, s3));
                }
                int rowL = wm * 32 + mf * 16 + g;
                atomicMin(&s_rmin[rowL],     fenc(m0v));
                atomicMin(&s_rmin[rowL + 8], fenc(m1v));
            }
            __syncthreads();
            #pragma unroll
            for (int mf = 0; mf < 2; ++mf) {
                int rowL0 = wm * 32 + mf * 16 + g;
                float thr0 = fdec(s_rmin[rowL0])     + DELTA;
                float thr1 = fdec(s_rmin[rowL0 + 8]) + DELTA;
                #pragma unroll
                for (int nf = 0; nf < 4; ++nf) {
                    int colL = wn * 32 + nf * 8 + qp;
                    #pragma unroll
                    for (int e = 0; e < 4; ++e) {
                        int cL = colL + (e & 1);
                        float sc = s_cn[cL] - 2.0f * acc[mf][nf][e];
                        float thr = (e < 2) ? thr0 : thr1;
                        if (sc < thr) {
                            int rowL = rowL0 + ((e >> 1) << 3);
                            int p = atomicAdd(&s_cnt[rowL], 1);
                            if (p < CAP)
                                g_cand[(m0 + rowL) * CAP + p] = (nt << 7) + cL;
                        }
                    }
                }
                #pragma unroll
                for (int nf = 0; nf < 4; ++nf)
                    #pragma unroll
                    for (int e = 0; e < 4; ++e) acc[mf][nf][e] = 0.f;
            }
        }

        // -------- issue chunk gc+3 (overwrites buffer last read at gc-1) --------
        int gn = gc + 3;
        if (gn < NCHUNK) {
            int nt2 = gn >> 4, kc2 = gn & 15, buf2 = gn & 3;
            #pragma unroll
            for (int it = 0; it < 2; ++it) {
                int idx = tid + (it << 8);
                int r = idx >> 2, i16 = idx & 3;
                CP_ASYNC16(sbase + SMP_B + buf2 * BBUF_B + r * (BSTRIDE * 2) + i16 * 16,
                           &g_cbbf[(long long)((nt2 << 7) + r) * kC + (kc2 << 5) + i16 * 8]);
            }
            CP_COMMIT();
        }
    }
    __syncthreads();
    if (tid < 64) g_ccnt[m0 + tid] = s_cnt[tid];
}

// ---------------- Phase 2: exact fp32 rescore of candidates (+ fused count) ----------------
__global__ void k_rescore(const float* __restrict__ cb) {
    int w = (blockIdx.x * blockDim.x + threadIdx.x) >> 5;
    int lane = threadIdx.x & 31;
    if (w >= kNT) return;
    float xr[16];
    #pragma unroll
    for (int i = 0; i < 16; i++) xr[i] = g_xT[(long long)w * kC + lane + 32 * i];
    int cnt = g_ccnt[w];
    float bd = 3.4e38f; int bj = 0;
    if (cnt <= CAP) {
        for (int ci = 0; ci < cnt; ci++) {
            int j = g_cand[(long long)w * CAP + ci];
            const float* cr = cb + (long long)j * kC;
            float s = 0.f;
            #pragma unroll
            for (int i = 0; i < 16; i++) s += xr[i] * cr[lane + 32 * i];
            #pragma unroll
            for (int o = 16; o; o >>= 1) s += __shfl_xor_sync(0xffffffffu, s, o);
            float d = g_cnorm[j] - 2.0f * s;
            if (d < bd || (d == bd && j < bj)) { bd = d; bj = j; }
        }
    } else {  // overflow fallback: deterministic full scan
        for (int j = 0; j < kNB; j++) {
            const float* cr = cb + (long long)j * kC;
            float s = 0.f;
            #pragma unroll
            for (int i = 0; i < 16; i++) s += xr[i] * cr[lane + 32 * i];
            #pragma unroll
            for (int o = 16; o; o >>= 1) s += __shfl_xor_sync(0xffffffffu, s, o);
            float d = g_cnorm[j] - 2.0f * s;
            if (d < bd || (d == bd && j < bj)) { bd = d; bj = j; }
        }
    }
    if (lane == 0) {
        g_idx[w] = bj;
        atomicAdd(&g_count[bj], 1);
    }
}

// ---------------- scan / scatter ----------------
__global__ void k_scan() {
    __shared__ int p[1024];
    int tid = threadIdx.x;
    int a = g_count[2 * tid], b = g_count[2 * tid + 1];
    p[tid] = a + b;
    __syncthreads();
    for (int off = 1; off < 1024; off <<= 1) {
        int v = (tid >= off) ? p[tid - off] : 0;
        __syncthreads();
        p[tid] += v;
        __syncthreads();
    }
    int base = p[tid] - a - b;
    g_off[2 * tid] = base;       g_off[2 * tid + 1] = base + a;
    g_pos[2 * tid] = base;       g_pos[2 * tid + 1] = base + a;
    if (tid == 1023) g_off[kNB] = p[tid];
}

__global__ void k_scatter() {
    int i = blockIdx.x * blockDim.x + threadIdx.x;
    if (i < kNT) {
        int j = g_idx[i];
        int pos = atomicAdd(&g_pos[j], 1);
        g_tok[pos] = i;
    }
}

// ---------------- EMA update (parallel odd-even sort) ----------------
__global__ void k_update(const float* __restrict__ code_sum,
                         const float* __restrict__ code_count,
                         float* __restrict__ out) {
    __shared__ int toks[TOKCAP];
    int j = blockIdx.x, tid = threadIdx.x;
    int beg = g_off[j], end = g_off[j + 1];
    int cnt = end - beg;
    int m = cnt < TOKCAP ? cnt : TOKCAP;
    for (int i = tid; i < m; i += 128) toks[i] = g_tok[beg + i];
    __syncthreads();
    for (int phase = 0; phase < m; ++phase) {
        int start = phase & 1;
        for (int k2 = 2 * tid + start; k2 + 1 < m; k2 += 256) {
            int a2 = toks[k2], b2 = toks[k2 + 1];
            if (a2 > b2) { toks[k2] = b2; toks[k2 + 1] = a2; }
        }
        __syncthreads();
    }

    int c = tid * 4;
    float4 acc = make_float4(0.f, 0.f, 0.f, 0.f);
    for (int i = 0; i < m; i++) {
        float4 v = *(const float4*)&g_xT[(long long)toks[i] * kC + c];
        acc.x += v.x; acc.y += v.y; acc.z += v.z; acc.w += v.w;
    }
    for (int i = m; i < cnt; i++) {
        float4 v = *(const float4*)&g_xT[(long long)g_tok[beg + i] * kC + c];
        acc.x += v.x; acc.y += v.y; acc.z += v.z; acc.w += v.w;
    }

    float MU = mu_f(), OMM = omm_f();
    float cema = MU * code_count[j] + OMM * (float)cnt;
    float4 os = *(const float4*)&code_sum[(long long)j * kC + c];
    float4 sema;
    sema.x = MU * os.x + OMM * acc.x;
    sema.y = MU * os.y + OMM * acc.y;
    sema.z = MU * os.z + OMM * acc.z;
    sema.w = MU * os.w + OMM * acc.w;
    float denom = fmaxf(cema, 1e-10f);
    bool usage = (cema >= 1.0f);
    float4 nb;
    if (usage) {
        nb.x = sema.x / denom; nb.y = sema.y / denom;
        nb.z = sema.z / denom; nb.w = sema.w / denom;
    } else {
        nb = *(const float4*)&g_xT[(long long)j * kC + c];
    }
    long long o1 = O_CB + (long long)j * kC + c;
    out[o1 + 0] = nb.x; out[o1 + 1] = nb.y; out[o1 + 2] = nb.z; out[o1 + 3] = nb.w;
    long long o2 = O_SUM + (long long)j * kC + c;
    out[o2 + 0] = sema.x; out[o2 + 1] = sema.y; out[o2 + 2] = sema.z; out[o2 + 3] = sema.w;
    if (tid == 0) out[O_CNT + j] = cema;
}

// ---------------- x_d_out + commit loss (coalesced: 32 t x 512 c per block) ----------------
__global__ void k_output(const float* __restrict__ x,
                         const float* __restrict__ cb,
                         float* __restrict__ out) {
    extern __shared__ float cbs[];          // 32 rows x 517 floats
    __shared__ float wsum[8];
    int b = blockIdx.x, tid = threadIdx.x;
    int n  = b >> 5;
    int t0 = (b & 31) << 5;
    int i0 = n * kT + t0;
    {
        int r = tid >> 3, lane8 = tid & 7;
        int code = g_idx[i0 + r];
        const float* src = cb + (long long)code * kC;
        float* dst = cbs + r * 517;
        for (int q = lane8 * 4; q < kC; q += 32) {
            float4 v = *(const float4*)(src + q);
            dst[q] = v.x; dst[q + 1] = v.y; dst[q + 2] = v.z; dst[q + 3] = v.w;
        }
    }
    __syncthreads();

    int w = tid >> 5, lane = tid & 31;
    const float* crow = cbs + lane * 517;
    float part = 0.f;
    for (int c = w; c < kC; c += 8) {
        long long off = ((long long)n * kC + c) * kT + t0 + lane;
        float xv = x[off];
        float cv = crow[c];
        float d = cv - xv;
        out[O_XD + off] = xv + d;
        part += d * d;
    }
    #pragma unroll
    for (int o = 16; o; o >>= 1) part += __shfl_xor_sync(0xffffffffu, part, o);
    if (lane == 0) wsum[w] = part;
    __syncthreads();
    if (tid == 0) {
        float s = 0.f;
        for (int q = 0; q < 8; q++) s += wsum[q];
        atomicAdd(&g_commit, (double)s);
    }
}

__global__ void k_scalars(float* __restrict__ out) {
    __shared__ float wsum[8];
    int tid = threadIdx.x;
    float total = (float)kNT + 1e-10f;
    float s = 0.f;
    for (int j = tid; j < kNB; j += 256) {
        float p = (float)g_count[j] / total;
        s += p * logf(p + 1e-7f);
    }
    #pragma unroll
    for (int o = 16; o; o >>= 1) s += __shfl_xor_sync(0xffffffffu, s, o);
    if ((tid & 31) == 0) wsum[tid >> 5] = s;
    __syncthreads();
    if (tid == 0) {
        float S = 0.f;
        for (int w = 0; w < 8; w++) S += wsum[w];
        out[O_PERP]   = expf(-S);
        out[O_COMMIT] = (float)(g_commit / ((double)kNT * (double)kC));
    }
}

// ---------------- launch ----------------
extern "C" void kernel_launch(void* const* d_in, const int* in_sizes, int n_in,
                              void* d_out, int out_size) {
    const float* x          = (const float*)d_in[0];
    const float* cb         = (const float*)d_in[1];
    const float* code_sum   = (const float*)d_in[2];
    const float* code_count = (const float*)d_in[3];
    float* out = (float*)d_out;

    const int outSmem = 32 * 517 * 4;
    cudaFuncSetAttribute(k_phase1, cudaFuncAttributeMaxDynamicSharedMemorySize, SMP_TOT);
    cudaFuncSetAttribute(k_output, cudaFuncAttributeMaxDynamicSharedMemorySize, outSmem);

    k_zero<<<8, 256>>>();
    k_transpose<<<dim3(kT / 32, kC / 32, kN), dim3(32, 8)>>>(x);
    k_cnorm<<<kNB / 4, dim3(32, 4)>>>(cb);
    k_phase1<<<kNT / 64, 256, SMP_TOT>>>();
    k_rescore<<<kNT / 8, 256>>>(cb);
    k_scan<<<1, 1024>>>();
    k_scatter<<<kNT / 256, 256>>>();
    k_update<<<kNB, 128>>>(code_sum, code_count, out);
    k_output<<<kNT / 32, 256, outSmem>>>(x, cb, out);
    k_scalars<<<1, 256>>>(out);
}